// round 11
// baseline (speedup 1.0000x reference)
#include <cuda_runtime.h>
#include <cuda_bf16.h>
#include <cstdint>

// ---------------- problem dims ------------------------------------------------
#define NB   32
#define NS   512
#define ND   512
#define NH   8
#define NDK  64
#define NFF  200
#define NFP  256            // padded FF width
#define NM   (NB * NS)      // 16384 rows
#define LN_N (NS * ND)      // 262144 elems per batch for 2-D LayerNorm
#define LN_CH 16            // chunks per batch for split LayerNorm
#define LN_CN (LN_N / LN_CH)  // 16384 elems per chunk

// ---------------- arena (single static device allocation) ---------------------
constexpr size_t SZ_BF_MD = (size_t)NM * ND * 2;        // [16384,512] bf16
constexpr size_t SZ_BF_DD = (size_t)ND * ND * 2;        // [512,512]  bf16
constexpr size_t SZ_BF_W1 = (size_t)NFP * ND * 2;
constexpr size_t SZ_BF_W2 = (size_t)NFP * NFP * 2;
constexpr size_t SZ_BF_W3 = (size_t)ND * NFP * 2;
constexpr size_t SZ_F_MD  = (size_t)NM * ND * 4;
constexpr size_t SZ_BF_MF = (size_t)NM * NFP * 2;

constexpr size_t O_XH = 0,                 O_XL = O_XH + SZ_BF_MD;
constexpr size_t O_WQH = O_XL + SZ_BF_MD,  O_WQL = O_WQH + SZ_BF_DD;
constexpr size_t O_WKH = O_WQL + SZ_BF_DD, O_WKL = O_WKH + SZ_BF_DD;
constexpr size_t O_WVH = O_WKL + SZ_BF_DD, O_WVL = O_WVH + SZ_BF_DD;
constexpr size_t O_WOH = O_WVL + SZ_BF_DD, O_WOL = O_WOH + SZ_BF_DD;
constexpr size_t O_W1H = O_WOL + SZ_BF_DD, O_W1L = O_W1H + SZ_BF_W1;
constexpr size_t O_W2H = O_W1L + SZ_BF_W1, O_W2L = O_W2H + SZ_BF_W2;
constexpr size_t O_W3H = O_W2L + SZ_BF_W2, O_W3L = O_W3H + SZ_BF_W3;
constexpr size_t O_B1P = O_W3L + SZ_BF_W3, O_B2P = O_B1P + 1024;
constexpr size_t O_LNP = O_B2P + 1024;                       // 512 float2 partials
constexpr size_t O_QH  = O_LNP + 8192,     O_QL  = O_QH + SZ_BF_MD;
constexpr size_t O_KH  = O_QL + SZ_BF_MD,  O_KL  = O_KH + SZ_BF_MD;
constexpr size_t O_VTH = O_KL + SZ_BF_MD,  O_VTL = O_VTH + SZ_BF_MD;
constexpr size_t O_CCH = O_VTL + SZ_BF_MD, O_CCL = O_CCH + SZ_BF_MD;
constexpr size_t O_Y   = O_CCL + SZ_BF_MD;
constexpr size_t O_YH  = O_Y + SZ_F_MD,    O_YL  = O_YH + SZ_BF_MD;
constexpr size_t O_F1H = O_YL + SZ_BF_MD,  O_F1L = O_F1H + SZ_BF_MF;
constexpr size_t O_F2H = O_F1L + SZ_BF_MF, O_F2L = O_F2H + SZ_BF_MF;
constexpr size_t O_F3  = O_F2L + SZ_BF_MF;
constexpr size_t O_Y2  = O_F3 + SZ_F_MD;
constexpr size_t ARENA = O_Y2 + SZ_F_MD;

__device__ __align__(1024) unsigned char g_arena[ARENA];

// ---------------- helpers -----------------------------------------------------
__device__ __forceinline__ uint32_t su32(const void* p) {
    uint32_t a;
    asm("{ .reg .u64 t; cvta.to.shared.u64 t, %1; cvt.u32.u64 %0, t; }" : "=r"(a) : "l"(p));
    return a;
}
__device__ __forceinline__ void cpa16(uint32_t d, const void* s) {
    asm volatile("cp.async.ca.shared.global [%0], [%1], 16;" :: "r"(d), "l"(s));
}
__device__ __forceinline__ void cp_commit() {
    asm volatile("cp.async.commit_group;" ::: "memory");
}
__device__ __forceinline__ void ldm4(uint32_t* r, uint32_t a) {
    asm volatile("ldmatrix.sync.aligned.m8n8.x4.shared.b16 {%0,%1,%2,%3}, [%4];"
        : "=r"(r[0]), "=r"(r[1]), "=r"(r[2]), "=r"(r[3]) : "r"(a));
}
__device__ __forceinline__ void mma16816(float* c, const uint32_t* a, uint32_t b0, uint32_t b1) {
    asm volatile("mma.sync.aligned.m16n8k16.row.col.f32.bf16.bf16.f32 "
        "{%0,%1,%2,%3}, {%4,%5,%6,%7}, {%8,%9}, {%0,%1,%2,%3};"
        : "+f"(c[0]), "+f"(c[1]), "+f"(c[2]), "+f"(c[3])
        : "r"(a[0]), "r"(a[1]), "r"(a[2]), "r"(a[3]), "r"(b0), "r"(b1));
}
__device__ __forceinline__ void split2(float v, __nv_bfloat16& h, __nv_bfloat16& l) {
    h = __float2bfloat16(v);
    l = __float2bfloat16(v - __bfloat162float(h));
}
__device__ __forceinline__ uint32_t pack2(__nv_bfloat16 a, __nv_bfloat16 b) {
    return (uint32_t)__bfloat16_as_ushort(a) | ((uint32_t)__bfloat16_as_ushort(b) << 16);
}

// ---------------- bf16 HMMA GEMM: 128x128 block, 4 warps of 64x64 --------------
template<int MODE, bool RELU>
__global__ __launch_bounds__(128, 2)
void gemm_mma(const __nv_bfloat16* __restrict__ Ah, const __nv_bfloat16* __restrict__ Al,
              const __nv_bfloat16* __restrict__ Bh, const __nv_bfloat16* __restrict__ Bl,
              const float* __restrict__ bias, const float* __restrict__ Res,
              float* __restrict__ Cf, __nv_bfloat16* __restrict__ Chi, __nv_bfloat16* __restrict__ Clo,
              int K, int lda, int ldb, int ldc,
              float alpha)
{
    constexpr int LDS = 40;
    constexpr int A_H = 128 * LDS;
    constexpr int B_H = 128 * LDS;
    constexpr int STG = 2 * A_H + 2 * B_H;

    extern __shared__ __align__(16) __nv_bfloat16 sm[];
    const uint32_t sb = su32(sm);

    const int tid = threadIdx.x, wid = tid >> 5, lane = tid & 31;
    const int wm = wid >> 1, wn = wid & 1;
    const int bmat = lane >> 3, bmr = lane & 7;

    const int mBlk = blockIdx.y * 128, nBlk = blockIdx.x * 128;
    Ah += (long)mBlk * lda; Al += (long)mBlk * lda;
    Bh += (long)nBlk * ldb; Bl += (long)nBlk * ldb;

    auto stage_copy = [&](int t, int s) {
        const int kt = t * 32;
        const uint32_t st = sb + 2u * (uint32_t)(s * STG);
        #pragma unroll
        for (int j = 0; j < 4; j++) {
            const int i = tid + j * 128;
            const int r = i >> 2, cg = (i & 3) * 8;
            const long goA = (long)r * lda + kt + cg;
            const uint32_t dA = st + 2u * (uint32_t)(r * LDS + cg);
            cpa16(dA,            Ah + goA);
            cpa16(dA + 2u * A_H, Al + goA);
            const long goB = (long)r * ldb + kt + cg;
            const uint32_t dB = st + 2u * (uint32_t)(2 * A_H + r * LDS + cg);
            cpa16(dB,            Bh + goB);
            cpa16(dB + 2u * B_H, Bl + goB);
        }
        cp_commit();
    };

    float acc[4][8][4];
    #pragma unroll
    for (int i = 0; i < 4; i++)
        #pragma unroll
        for (int j = 0; j < 8; j++)
            #pragma unroll
            for (int q = 0; q < 4; q++) acc[i][j][q] = 0.f;

    const int nt = K / 32;
    stage_copy(0, 0);

    for (int t = 0; t < nt; t++) {
        if (t + 1 < nt) stage_copy(t + 1, (t + 1) & 1);
        if (t + 1 < nt) asm volatile("cp.async.wait_group 1;" ::: "memory");
        else            asm volatile("cp.async.wait_group 0;" ::: "memory");
        __syncthreads();

        const int s = t & 1;
        const uint32_t ab = sb + 2u * (uint32_t)(s * STG);
        const uint32_t bb = ab + 2u * (uint32_t)(2 * A_H);

        #pragma unroll
        for (int ks = 0; ks < 2; ks++) {
            const int acol = ks * 16 + (lane >> 4) * 8;
            uint32_t afh[4][4], afl[4][4];
            #pragma unroll
            for (int mt = 0; mt < 4; mt++) {
                const uint32_t ad = ab + 2u * (uint32_t)((wm * 64 + mt * 16 + (lane & 15)) * LDS + acol);
                ldm4(afh[mt], ad);
                ldm4(afl[mt], ad + 2u * A_H);
            }
            uint32_t bfh[16], bfl[16];
            #pragma unroll
            for (int p = 0; p < 4; p++) {
                const int n = wn * 64 + (p * 2 + (bmat >> 1)) * 8 + bmr;
                const int koff = ks * 16 + (bmat & 1) * 8;
                const uint32_t bd = bb + 2u * (uint32_t)(n * LDS + koff);
                ldm4(&bfh[p * 4], bd);
                ldm4(&bfl[p * 4], bd + 2u * B_H);
            }
            #pragma unroll
            for (int mt = 0; mt < 4; mt++) {
                #pragma unroll
                for (int n4 = 0; n4 < 8; n4++) {
                    const int bi = (n4 >> 1) * 4 + (n4 & 1) * 2;
                    mma16816(acc[mt][n4], afh[mt], bfh[bi], bfh[bi + 1]);
                    mma16816(acc[mt][n4], afh[mt], bfl[bi], bfl[bi + 1]);
                    mma16816(acc[mt][n4], afl[mt], bfh[bi], bfh[bi + 1]);
                }
            }
        }
        __syncthreads();
    }

    const int mW = mBlk + wm * 64;
    const int nW = nBlk + wn * 64;
    #pragma unroll
    for (int mt = 0; mt < 4; mt++) {
        #pragma unroll
        for (int n4 = 0; n4 < 8; n4++) {
            const int n0 = nW + n4 * 8 + (lane & 3) * 2;
            float bx = 0.f, by = 0.f;
            if (bias) { bx = bias[n0]; by = bias[n0 + 1]; }
            #pragma unroll
            for (int half = 0; half < 2; half++) {
                const int m = mW + mt * 16 + half * 8 + (lane >> 2);
                float v0 = acc[mt][n4][half * 2 + 0] + bx;
                float v1 = acc[mt][n4][half * 2 + 1] + by;
                v0 *= alpha; v1 *= alpha;
                if (RELU) { v0 = fmaxf(v0, 0.f); v1 = fmaxf(v1, 0.f); }
                if (MODE == 0) {
                    const long ro = (long)m * ldc + n0;
                    if (Res) { v0 += Res[ro]; v1 += Res[ro + 1]; }
                    *reinterpret_cast<float2*>(Cf + ro) = make_float2(v0, v1);
                } else if (MODE == 1) {
                    const long ro = (long)m * ldc + n0;
                    __nv_bfloat16 h0, h1, l0, l1;
                    split2(v0, h0, l0); split2(v1, h1, l1);
                    *reinterpret_cast<uint32_t*>(Chi + ro) = pack2(h0, h1);
                    *reinterpret_cast<uint32_t*>(Clo + ro) = pack2(l0, l1);
                } else {   // MODE 2: vt[(b*512 + n)*512 + t]
                    const int bq = m >> 9, tq = m & 511;
                    __nv_bfloat16 h0, h1, l0, l1;
                    split2(v0, h0, l0); split2(v1, h1, l1);
                    const long a0 = ((long)(bq * 512 + n0)) * 512 + tq;
                    const long a1 = a0 + 512;
                    Chi[a0] = h0; Clo[a0] = l0;
                    Chi[a1] = h1; Clo[a1] = l1;
                }
            }
        }
    }
}

// ---------------- fused flash attention (unchanged from passing R10) -----------
__global__ __launch_bounds__(512, 1)
void flash_attn(const __nv_bfloat16* __restrict__ Qh, const __nv_bfloat16* __restrict__ Ql,
                const __nv_bfloat16* __restrict__ Kh, const __nv_bfloat16* __restrict__ Kl,
                const __nv_bfloat16* __restrict__ Vh, const __nv_bfloat16* __restrict__ Vl,
                __nv_bfloat16* __restrict__ Ch, __nv_bfloat16* __restrict__ Cl)
{
    constexpr int oQH = 0,      oQL = 18432;
    constexpr int oKH = 36864,  oKL = 55296;
    constexpr int oVH = 73728,  oVL = 91136;
    constexpr int oPH = 108544, oPL = 143360;
    constexpr int oPM = 178176, oPS = 180224;
    constexpr int oM  = 182272, oL = 182784, oS = 183296;
    extern __shared__ __align__(16) char smf[];
    const uint32_t sb = su32(smf);
    float* pm   = reinterpret_cast<float*>(smf + oPM);
    float* ps   = reinterpret_cast<float*>(smf + oPS);
    float* mrow = reinterpret_cast<float*>(smf + oM);
    float* lrow = reinterpret_cast<float*>(smf + oL);
    float* srow = reinterpret_cast<float*>(smf + oS);

    const int tid = threadIdx.x, wid = tid >> 5, lane = tid & 31;
    const int wm = wid >> 2, wn = wid & 3;
    const int om = wid >> 1, on = wid & 1;
    const int qt = blockIdx.x, z = blockIdx.y;
    const int b = z >> 3, h = z & 7;
    const int bmat = lane >> 3, bmr = lane & 7;

    {
        const long base = (long)(b * 512 + qt * 128) * 512 + h * 64;
        for (int i = tid; i < 1024; i += 512) {
            const int r = i >> 3, c8 = (i & 7) * 8;
            const long go = base + (long)r * 512 + c8;
            *reinterpret_cast<uint4*>(smf + oQH + 2 * (r * 72 + c8)) =
                *reinterpret_cast<const uint4*>(Qh + go);
            *reinterpret_cast<uint4*>(smf + oQL + 2 * (r * 72 + c8)) =
                *reinterpret_cast<const uint4*>(Ql + go);
        }
    }
    if (tid < 128) { mrow[tid] = -1e30f; lrow[tid] = 0.f; }

    float acc_o[4][4];
    #pragma unroll
    for (int i = 0; i < 4; i++)
        #pragma unroll
        for (int j = 0; j < 4; j++) acc_o[i][j] = 0.f;

    __syncthreads();

    for (int kb = 0; kb < 4; kb++) {
        {
            const long kbase = (long)(b * 512 + kb * 128) * 512 + h * 64;
            for (int i = tid; i < 1024; i += 512) {
                const int r = i >> 3, c8 = (i & 7) * 8;
                const long go = kbase + (long)r * 512 + c8;
                *reinterpret_cast<uint4*>(smf + oKH + 2 * (r * 72 + c8)) =
                    *reinterpret_cast<const uint4*>(Kh + go);
                *reinterpret_cast<uint4*>(smf + oKL + 2 * (r * 72 + c8)) =
                    *reinterpret_cast<const uint4*>(Kl + go);
            }
            const long vbase = (long)(b * 512 + h * 64) * 512 + kb * 128;
            for (int i = tid; i < 1024; i += 512) {
                const int r = i >> 4, c8 = (i & 15) * 8;
                const long go = vbase + (long)r * 512 + c8;
                *reinterpret_cast<uint4*>(smf + oVH + 2 * (r * 136 + c8)) =
                    *reinterpret_cast<const uint4*>(Vh + go);
                *reinterpret_cast<uint4*>(smf + oVL + 2 * (r * 136 + c8)) =
                    *reinterpret_cast<const uint4*>(Vl + go);
            }
        }
        __syncthreads();

        float acc_s[2][4][4];
        #pragma unroll
        for (int i = 0; i < 2; i++)
            #pragma unroll
            for (int j = 0; j < 4; j++)
                #pragma unroll
                for (int q = 0; q < 4; q++) acc_s[i][j][q] = 0.f;

        #pragma unroll
        for (int ks = 0; ks < 4; ks++) {
            const int acol = ks * 16 + (lane >> 4) * 8;
            uint32_t afh[2][4], afl[2][4];
            #pragma unroll
            for (int mt = 0; mt < 2; mt++) {
                const uint32_t ad = sb + oQH +
                    2u * (uint32_t)((wm * 32 + mt * 16 + (lane & 15)) * 72 + acol);
                ldm4(afh[mt], ad);
                ldm4(afl[mt], ad + (oQL - oQH));
            }
            uint32_t bfh[8], bfl[8];
            #pragma unroll
            for (int p = 0; p < 2; p++) {
                const int n = wn * 32 + (p * 2 + (bmat >> 1)) * 8 + bmr;
                const int koff = ks * 16 + (bmat & 1) * 8;
                const uint32_t bd = sb + oKH + 2u * (uint32_t)(n * 72 + koff);
                ldm4(&bfh[p * 4], bd);
                ldm4(&bfl[p * 4], bd + (oKL - oKH));
            }
            #pragma unroll
            for (int mt = 0; mt < 2; mt++) {
                #pragma unroll
                for (int n4 = 0; n4 < 4; n4++) {
                    const int bi = (n4 >> 1) * 4 + (n4 & 1) * 2;
                    mma16816(acc_s[mt][n4], afh[mt], bfh[bi], bfh[bi + 1]);
                    mma16816(acc_s[mt][n4], afh[mt], bfl[bi], bfl[bi + 1]);
                    mma16816(acc_s[mt][n4], afl[mt], bfh[bi], bfh[bi + 1]);
                }
            }
        }

        #pragma unroll
        for (int mt = 0; mt < 2; mt++) {
            #pragma unroll
            for (int half = 0; half < 2; half++) {
                float vmax = -1e30f;
                #pragma unroll
                for (int n4 = 0; n4 < 4; n4++)
                    vmax = fmaxf(vmax, fmaxf(acc_s[mt][n4][half * 2], acc_s[mt][n4][half * 2 + 1]));
                vmax = fmaxf(vmax, __shfl_xor_sync(0xffffffffu, vmax, 1));
                vmax = fmaxf(vmax, __shfl_xor_sync(0xffffffffu, vmax, 2));
                if ((lane & 3) == 0) {
                    const int row = wm * 32 + mt * 16 + half * 8 + (lane >> 2);
                    pm[row * 4 + wn] = vmax;
                }
            }
        }
        __syncthreads();
        if (tid < 128) {
            const float mb = fmaxf(fmaxf(pm[tid * 4], pm[tid * 4 + 1]),
                                   fmaxf(pm[tid * 4 + 2], pm[tid * 4 + 3]));
            const float mn = fmaxf(mrow[tid], mb);
            srow[tid] = __expf(mrow[tid] - mn);
            mrow[tid] = mn;
        }
        __syncthreads();

        #pragma unroll
        for (int mt = 0; mt < 2; mt++) {
            #pragma unroll
            for (int half = 0; half < 2; half++) {
                const int row = wm * 32 + mt * 16 + half * 8 + (lane >> 2);
                const float mi = mrow[row];
                float rs = 0.f;
                #pragma unroll
                for (int n4 = 0; n4 < 4; n4++) {
                    const float p0 = __expf(acc_s[mt][n4][half * 2 + 0] - mi);
                    const float p1 = __expf(acc_s[mt][n4][half * 2 + 1] - mi);
                    rs += p0 + p1;
                    const int col = wn * 32 + n4 * 8 + (lane & 3) * 2;
                    __nv_bfloat16 h0, h1, l0, l1;
                    split2(p0, h0, l0); split2(p1, h1, l1);
                    *reinterpret_cast<uint32_t*>(smf + oPH + 2 * (row * 136 + col)) = pack2(h0, h1);
                    *reinterpret_cast<uint32_t*>(smf + oPL + 2 * (row * 136 + col)) = pack2(l0, l1);
                }
                rs += __shfl_xor_sync(0xffffffffu, rs, 1);
                rs += __shfl_xor_sync(0xffffffffu, rs, 2);
                if ((lane & 3) == 0) ps[row * 4 + wn] = rs;
            }
        }
        __syncthreads();

        if (tid < 128)
            lrow[tid] = lrow[tid] * srow[tid] +
                        (ps[tid * 4] + ps[tid * 4 + 1] + ps[tid * 4 + 2] + ps[tid * 4 + 3]);

        {
            const int r0 = om * 16 + (lane >> 2);
            const float s0 = srow[r0], s1 = srow[r0 + 8];
            #pragma unroll
            for (int n4 = 0; n4 < 4; n4++) {
                acc_o[n4][0] *= s0; acc_o[n4][1] *= s0;
                acc_o[n4][2] *= s1; acc_o[n4][3] *= s1;
            }
        }

        #pragma unroll
        for (int ks2 = 0; ks2 < 8; ks2++) {
            const int acol = ks2 * 16 + (lane >> 4) * 8;
            uint32_t pah[4], pal[4];
            {
                const uint32_t ad = sb + oPH +
                    2u * (uint32_t)((om * 16 + (lane & 15)) * 136 + acol);
                ldm4(pah, ad);
                ldm4(pal, ad + (oPL - oPH));
            }
            uint32_t bfh[8], bfl[8];
            #pragma unroll
            for (int p = 0; p < 2; p++) {
                const int n = on * 32 + (p * 2 + (bmat >> 1)) * 8 + bmr;
                const int koff = ks2 * 16 + (bmat & 1) * 8;
                const uint32_t bd = sb + oVH + 2u * (uint32_t)(n * 136 + koff);
                ldm4(&bfh[p * 4], bd);
                ldm4(&bfl[p * 4], bd + (oVL - oVH));
            }
            #pragma unroll
            for (int n4 = 0; n4 < 4; n4++) {
                const int bi = (n4 >> 1) * 4 + (n4 & 1) * 2;
                mma16816(acc_o[n4], pah, bfh[bi], bfh[bi + 1]);
                mma16816(acc_o[n4], pah, bfl[bi], bfl[bi + 1]);
                mma16816(acc_o[n4], pal, bfh[bi], bfh[bi + 1]);
            }
        }
        __syncthreads();
    }

    if (tid < 128) srow[tid] = 1.f / lrow[tid];
    __syncthreads();
    {
        const int r0 = om * 16 + (lane >> 2);
        const float i0 = srow[r0], i1 = srow[r0 + 8];
        const long gq = (long)(b * 512 + qt * 128);
        #pragma unroll
        for (int n4 = 0; n4 < 4; n4++) {
            const int c0 = on * 32 + n4 * 8 + (lane & 3) * 2;
            const float v00 = acc_o[n4][0] * i0, v01 = acc_o[n4][1] * i0;
            const float v10 = acc_o[n4][2] * i1, v11 = acc_o[n4][3] * i1;
            const long a0 = (gq + r0) * 512 + h * 64 + c0;
            const long a1 = (gq + r0 + 8) * 512 + h * 64 + c0;
            __nv_bfloat16 h0, h1, l0, l1;
            split2(v00, h0, l0); split2(v01, h1, l1);
            *reinterpret_cast<uint32_t*>(Ch + a0) = pack2(h0, h1);
            *reinterpret_cast<uint32_t*>(Cl + a0) = pack2(l0, l1);
            split2(v10, h0, l0); split2(v11, h1, l1);
            *reinterpret_cast<uint32_t*>(Ch + a1) = pack2(h0, h1);
            *reinterpret_cast<uint32_t*>(Cl + a1) = pack2(l0, l1);
        }
    }
}

// ---------------- fp32 -> bf16 hi/lo split with zero-padding -------------------
__global__ void split_kernel(const float* __restrict__ src, __nv_bfloat16* __restrict__ hi,
                             __nv_bfloat16* __restrict__ lo, int rs, int cs, int rd, int cd)
{
    const long idx4 = ((long)blockIdx.x * blockDim.x + threadIdx.x) * 4;
    if (idx4 >= (long)rd * cd) return;
    const int r = (int)(idx4 / cd), c = (int)(idx4 % cd);
    float4 v = make_float4(0.f, 0.f, 0.f, 0.f);
    if (r < rs && c < cs) v = *reinterpret_cast<const float4*>(src + (long)r * cs + c);
    __nv_bfloat16 h0, h1, h2, h3, l0, l1, l2, l3;
    split2(v.x, h0, l0); split2(v.y, h1, l1); split2(v.z, h2, l2); split2(v.w, h3, l3);
    *reinterpret_cast<uint2*>(hi + idx4) = make_uint2(pack2(h0, h1), pack2(h2, h3));
    *reinterpret_cast<uint2*>(lo + idx4) = make_uint2(pack2(l0, l1), pack2(l2, l3));
}

__global__ void pad_bias2(const float* __restrict__ s1, float* __restrict__ d1,
                          const float* __restrict__ s2, float* __restrict__ d2, int n) {
    const int i = threadIdx.x;
    if (blockIdx.x == 0) d1[i] = (i < n) ? s1[i] : 0.f;
    else                 d2[i] = (i < n) ? s2[i] : 0.f;
}

// ---------------- split 2-D LayerNorm: full-chip two-phase ---------------------
// grid = NB*LN_CH CTAs; batch = bid>>4, chunk = bid&15; 256 threads.
__global__ __launch_bounds__(256)
void ln_partial(const float* __restrict__ X, float2* __restrict__ part)
{
    const int batch = blockIdx.x >> 4, chunk = blockIdx.x & (LN_CH - 1);
    const long base = (long)batch * LN_N + (long)chunk * LN_CN;
    float s1 = 0.f, s2 = 0.f;
    #pragma unroll
    for (int j = 0; j < LN_CN / 1024; j++) {
        const int i = (threadIdx.x + j * 256) * 4;
        float4 v = *reinterpret_cast<const float4*>(X + base + i);
        s1 += (v.x + v.y) + (v.z + v.w);
        s2 += (v.x*v.x + v.y*v.y) + (v.z*v.z + v.w*v.w);
    }
    __shared__ float r1[8], r2[8];
    const int lane = threadIdx.x & 31, wid = threadIdx.x >> 5;
    #pragma unroll
    for (int o = 16; o; o >>= 1) {
        s1 += __shfl_xor_sync(0xffffffffu, s1, o);
        s2 += __shfl_xor_sync(0xffffffffu, s2, o);
    }
    if (!lane) { r1[wid] = s1; r2[wid] = s2; }
    __syncthreads();
    if (threadIdx.x == 0) {
        float t1 = 0.f, t2 = 0.f;
        #pragma unroll
        for (int w = 0; w < 8; w++) { t1 += r1[w]; t2 += r2[w]; }
        part[blockIdx.x] = make_float2(t1, t2);
    }
}

template<bool PAIR>
__global__ __launch_bounds__(256)
void ln_norm(const float* __restrict__ X, const float* __restrict__ gamma,
             const float* __restrict__ beta, const float2* __restrict__ part,
             float* __restrict__ out, __nv_bfloat16* __restrict__ oh,
             __nv_bfloat16* __restrict__ ol)
{
    const int batch = blockIdx.x >> 4, chunk = blockIdx.x & (LN_CH - 1);
    const long base = (long)batch * LN_N + (long)chunk * LN_CN;
    const long gbase = (long)chunk * LN_CN;   // gamma/beta index within (S,D)

    __shared__ float stats[2];
    if (threadIdx.x == 0) {
        float t1 = 0.f, t2 = 0.f;
        #pragma unroll
        for (int c = 0; c < LN_CH; c++) {
            const float2 p = part[batch * LN_CH + c];
            t1 += p.x; t2 += p.y;
        }
        const float mean = t1 / (float)LN_N;
        const float var  = t2 / (float)LN_N - mean * mean;
        stats[0] = mean;
        stats[1] = rsqrtf(var + 1e-5f);
    }
    __syncthreads();
    const float mean = stats[0], rstd = stats[1];

    #pragma unroll
    for (int j = 0; j < LN_CN / 1024; j++) {
        const int i = (threadIdx.x + j * 256) * 4;
        float4 v = *reinterpret_cast<const float4*>(X + base + i);
        float4 g  = *reinterpret_cast<const float4*>(gamma + gbase + i);
        float4 bt = *reinterpret_cast<const float4*>(beta  + gbase + i);
        float4 o;
        o.x = (v.x - mean) * rstd * g.x + bt.x;
        o.y = (v.y - mean) * rstd * g.y + bt.y;
        o.z = (v.z - mean) * rstd * g.z + bt.z;
        o.w = (v.w - mean) * rstd * g.w + bt.w;
        *reinterpret_cast<float4*>(out + base + i) = o;
        if (PAIR) {
            __nv_bfloat16 h0, h1, h2, h3, l0, l1, l2, l3;
            split2(o.x, h0, l0); split2(o.y, h1, l1); split2(o.z, h2, l2); split2(o.w, h3, l3);
            *reinterpret_cast<uint2*>(oh + base + i) = make_uint2(pack2(h0, h1), pack2(h2, h3));
            *reinterpret_cast<uint2*>(ol + base + i) = make_uint2(pack2(l0, l1), pack2(l2, l3));
        }
    }
}

// ---------------- launch --------------------------------------------------------
extern "C" void kernel_launch(void* const* d_in, const int* in_sizes, int n_in,
                              void* d_out, int out_size)
{
    const float* x  = (const float*)d_in[0];
    const float* Wq = (const float*)d_in[1];
    const float* bq = (const float*)d_in[2];
    const float* Wk = (const float*)d_in[3];
    const float* bk = (const float*)d_in[4];
    const float* Wv = (const float*)d_in[5];
    const float* bv = (const float*)d_in[6];
    const float* Wo = (const float*)d_in[7];
    const float* bo = (const float*)d_in[8];
    const float* W1 = (const float*)d_in[9];
    const float* b1 = (const float*)d_in[10];
    const float* W2 = (const float*)d_in[11];
    const float* b2 = (const float*)d_in[12];
    const float* W3 = (const float*)d_in[13];
    const float* b3 = (const float*)d_in[14];
    const float* gamma = (const float*)d_in[15];
    const float* beta  = (const float*)d_in[16];
    float* out = (float*)d_out;

    unsigned char* ar;
    cudaGetSymbolAddress((void**)&ar, g_arena);
    #define BF(o) reinterpret_cast<__nv_bfloat16*>(ar + (o))
    #define FP(o) reinterpret_cast<float*>(ar + (o))
    float2* lnp = reinterpret_cast<float2*>(ar + O_LNP);

    const int SMG  = 2 * (2 * 128 * 40 + 2 * 128 * 40) * 2;   // 81920
    const int SMFL = 183808;
    cudaFuncSetAttribute((const void*)gemm_mma<0, false>, cudaFuncAttributeMaxDynamicSharedMemorySize, SMG);
    cudaFuncSetAttribute((const void*)gemm_mma<1, false>, cudaFuncAttributeMaxDynamicSharedMemorySize, SMG);
    cudaFuncSetAttribute((const void*)gemm_mma<1, true >, cudaFuncAttributeMaxDynamicSharedMemorySize, SMG);
    cudaFuncSetAttribute((const void*)gemm_mma<2, false>, cudaFuncAttributeMaxDynamicSharedMemorySize, SMG);
    cudaFuncSetAttribute((const void*)flash_attn, cudaFuncAttributeMaxDynamicSharedMemorySize, SMFL);

    // ---- splits (fp32 -> bf16 hi/lo, with padding) ----
    auto g4 = [](long n) { return (unsigned)((n / 4 + 255) / 256); };
    split_kernel<<<g4((long)NM*ND),   256>>>(x,  BF(O_XH),  BF(O_XL),  NM, ND, NM, ND);
    split_kernel<<<g4((long)ND*ND),   256>>>(Wq, BF(O_WQH), BF(O_WQL), ND, ND, ND, ND);
    split_kernel<<<g4((long)ND*ND),   256>>>(Wk, BF(O_WKH), BF(O_WKL), ND, ND, ND, ND);
    split_kernel<<<g4((long)ND*ND),   256>>>(Wv, BF(O_WVH), BF(O_WVL), ND, ND, ND, ND);
    split_kernel<<<g4((long)ND*ND),   256>>>(Wo, BF(O_WOH), BF(O_WOL), ND, ND, ND, ND);
    split_kernel<<<g4((long)NFP*ND),  256>>>(W1, BF(O_W1H), BF(O_W1L), NFF, ND,  NFP, ND);
    split_kernel<<<g4((long)NFP*NFP), 256>>>(W2, BF(O_W2H), BF(O_W2L), NFF, NFF, NFP, NFP);
    split_kernel<<<g4((long)ND*NFP),  256>>>(W3, BF(O_W3H), BF(O_W3L), ND,  NFF, ND,  NFP);
    pad_bias2<<<2, 256>>>(b1, FP(O_B1P), b2, FP(O_B2P), NFF);

    // ---- 1) Q/K/V projections (q pre-scaled by 1/8; v written transposed) ----
    {
        dim3 grid(4, 128, 1);
        gemm_mma<1, false><<<grid, 128, SMG>>>(
            BF(O_XH), BF(O_XL), BF(O_WQH), BF(O_WQL), bq, nullptr,
            nullptr, BF(O_QH), BF(O_QL), ND, ND, ND, ND, 0.125f);
        gemm_mma<1, false><<<grid, 128, SMG>>>(
            BF(O_XH), BF(O_XL), BF(O_WKH), BF(O_WKL), bk, nullptr,
            nullptr, BF(O_KH), BF(O_KL), ND, ND, ND, ND, 1.f);
        gemm_mma<2, false><<<grid, 128, SMG>>>(
            BF(O_XH), BF(O_XL), BF(O_WVH), BF(O_WVL), bv, nullptr,
            nullptr, BF(O_VTH), BF(O_VTL), ND, ND, ND, ND, 1.f);
    }

    // ---- 2-4) fused flash attention -> concat pairs ----
    {
        dim3 grid(4, NB * NH);
        flash_attn<<<grid, 512, SMFL>>>(
            BF(O_QH), BF(O_QL), BF(O_KH), BF(O_KL),
            BF(O_VTH), BF(O_VTL), BF(O_CCH), BF(O_CCL));
    }

    // ---- 5) y = concat @ Wo^T + bo + x  (fp32) ----
    {
        dim3 grid(4, 128, 1);
        gemm_mma<0, false><<<grid, 128, SMG>>>(
            BF(O_CCH), BF(O_CCL), BF(O_WOH), BF(O_WOL), bo, x,
            FP(O_Y), nullptr, nullptr, ND, ND, ND, ND, 1.f);
    }

    // ---- 6) y = LN(y) (split two-phase), also emit bf16 pair ----
    ln_partial<<<NB * LN_CH, 256>>>(FP(O_Y), lnp);
    ln_norm<true><<<NB * LN_CH, 256>>>(FP(O_Y), gamma, beta, lnp,
                                       FP(O_Y), BF(O_YH), BF(O_YL));

    // ---- 7) f1 = relu(y @ W1p^T + b1p) pair, N=256 ----
    {
        dim3 grid(2, 128, 1);
        gemm_mma<1, true><<<grid, 128, SMG>>>(
            BF(O_YH), BF(O_YL), BF(O_W1H), BF(O_W1L), FP(O_B1P), nullptr,
            nullptr, BF(O_F1H), BF(O_F1L), ND, ND, ND, NFP, 1.f);
    }
    // ---- 8) f2 = relu(f1 @ W2p^T + b2p) pair, K=N=256 ----
    {
        dim3 grid(2, 128, 1);
        gemm_mma<1, true><<<grid, 128, SMG>>>(
            BF(O_F1H), BF(O_F1L), BF(O_W2H), BF(O_W2L), FP(O_B2P), nullptr,
            nullptr, BF(O_F2H), BF(O_F2L), NFP, NFP, NFP, NFP, 1.f);
    }
    // ---- 9) f3 = f2 @ W3p^T + b3 + y  (fp32, residual folded) ----
    {
        dim3 grid(4, 128, 1);
        gemm_mma<0, false><<<grid, 128, SMG>>>(
            BF(O_F2H), BF(O_F2L), BF(O_W3H), BF(O_W3L), b3, FP(O_Y),
            FP(O_F3), nullptr, nullptr, NFP, NFP, NFP, ND, 1.f);
    }

    // ---- 10) y2 = LN(f3) (split two-phase) ----
    ln_partial<<<NB * LN_CH, 256>>>(FP(O_F3), lnp);
    ln_norm<false><<<NB * LN_CH, 256>>>(FP(O_F3), gamma, beta, lnp,
                                        FP(O_Y2), nullptr, nullptr);
    // ---- 11) out = LN(y2) (split two-phase) ----
    ln_partial<<<NB * LN_CH, 256>>>(FP(O_Y2), lnp);
    ln_norm<false><<<NB * LN_CH, 256>>>(FP(O_Y2), gamma, beta, lnp,
                                        out, nullptr, nullptr);
}

// round 12
// speedup vs baseline: 1.3692x; 1.3692x over previous
#include <cuda_runtime.h>
#include <cuda_bf16.h>
#include <cstdint>

// ---------------- problem dims ------------------------------------------------
#define NB   32
#define NS   512
#define ND   512
#define NH   8
#define NDK  64
#define NFF  200
#define NFP  256            // padded FF width
#define NM   (NB * NS)      // 16384 rows
#define LN_N (NS * ND)      // 262144 elems per batch for 2-D LayerNorm

// ---------------- arena (single static device allocation) ---------------------
constexpr size_t SZ_BF_MD = (size_t)NM * ND * 2;        // [16384,512] bf16
constexpr size_t SZ_BF_DD = (size_t)ND * ND * 2;        // [512,512]  bf16
constexpr size_t SZ_BF_W1 = (size_t)NFP * ND * 2;
constexpr size_t SZ_BF_W2 = (size_t)NFP * NFP * 2;
constexpr size_t SZ_BF_W3 = (size_t)ND * NFP * 2;
constexpr size_t SZ_F_MD  = (size_t)NM * ND * 4;
constexpr size_t SZ_BF_MF = (size_t)NM * NFP * 2;

constexpr size_t O_XH = 0,                 O_XL = O_XH + SZ_BF_MD;
constexpr size_t O_WQH = O_XL + SZ_BF_MD,  O_WQL = O_WQH + SZ_BF_DD;
constexpr size_t O_WKH = O_WQL + SZ_BF_DD, O_WKL = O_WKH + SZ_BF_DD;
constexpr size_t O_WVH = O_WKL + SZ_BF_DD, O_WVL = O_WVH + SZ_BF_DD;
constexpr size_t O_WOH = O_WVL + SZ_BF_DD, O_WOL = O_WOH + SZ_BF_DD;
constexpr size_t O_W1H = O_WOL + SZ_BF_DD, O_W1L = O_W1H + SZ_BF_W1;
constexpr size_t O_W2H = O_W1L + SZ_BF_W1, O_W2L = O_W2H + SZ_BF_W2;
constexpr size_t O_W3H = O_W2L + SZ_BF_W2, O_W3L = O_W3H + SZ_BF_W3;
constexpr size_t O_B1P = O_W3L + SZ_BF_W3, O_B2P = O_B1P + 1024;
constexpr size_t O_QH  = O_B2P + 1024,     O_QL  = O_QH + SZ_BF_MD;
constexpr size_t O_KH  = O_QL + SZ_BF_MD,  O_KL  = O_KH + SZ_BF_MD;
constexpr size_t O_VTH = O_KL + SZ_BF_MD,  O_VTL = O_VTH + SZ_BF_MD;
constexpr size_t O_CCH = O_VTL + SZ_BF_MD, O_CCL = O_CCH + SZ_BF_MD;
constexpr size_t O_Y   = O_CCL + SZ_BF_MD;
constexpr size_t O_YH  = O_Y + SZ_F_MD,    O_YL  = O_YH + SZ_BF_MD;
constexpr size_t O_F1H = O_YL + SZ_BF_MD,  O_F1L = O_F1H + SZ_BF_MF;
constexpr size_t O_F2H = O_F1L + SZ_BF_MF, O_F2L = O_F2H + SZ_BF_MF;
constexpr size_t O_F3  = O_F2L + SZ_BF_MF;
constexpr size_t O_Y2  = O_F3 + SZ_F_MD;
constexpr size_t ARENA = O_Y2 + SZ_F_MD;

__device__ __align__(1024) unsigned char g_arena[ARENA];

// ---------------- helpers -----------------------------------------------------
__device__ __forceinline__ uint32_t su32(const void* p) {
    uint32_t a;
    asm("{ .reg .u64 t; cvta.to.shared.u64 t, %1; cvt.u32.u64 %0, t; }" : "=r"(a) : "l"(p));
    return a;
}
__device__ __forceinline__ void cpa16(uint32_t d, const void* s) {
    asm volatile("cp.async.ca.shared.global [%0], [%1], 16;" :: "r"(d), "l"(s));
}
__device__ __forceinline__ void cp_commit() {
    asm volatile("cp.async.commit_group;" ::: "memory");
}
__device__ __forceinline__ void ldm4(uint32_t* r, uint32_t a) {
    asm volatile("ldmatrix.sync.aligned.m8n8.x4.shared.b16 {%0,%1,%2,%3}, [%4];"
        : "=r"(r[0]), "=r"(r[1]), "=r"(r[2]), "=r"(r[3]) : "r"(a));
}
__device__ __forceinline__ void mma16816(float* c, const uint32_t* a, uint32_t b0, uint32_t b1) {
    asm volatile("mma.sync.aligned.m16n8k16.row.col.f32.bf16.bf16.f32 "
        "{%0,%1,%2,%3}, {%4,%5,%6,%7}, {%8,%9}, {%0,%1,%2,%3};"
        : "+f"(c[0]), "+f"(c[1]), "+f"(c[2]), "+f"(c[3])
        : "r"(a[0]), "r"(a[1]), "r"(a[2]), "r"(a[3]), "r"(b0), "r"(b1));
}
__device__ __forceinline__ void split2(float v, __nv_bfloat16& h, __nv_bfloat16& l) {
    h = __float2bfloat16(v);
    l = __float2bfloat16(v - __bfloat162float(h));
}
__device__ __forceinline__ uint32_t pack2(__nv_bfloat16 a, __nv_bfloat16 b) {
    return (uint32_t)__bfloat16_as_ushort(a) | ((uint32_t)__bfloat16_as_ushort(b) << 16);
}

// ---------------- bf16 HMMA GEMM: 128x128 block, 4 warps of 64x64 --------------
template<int MODE, bool RELU>
__global__ __launch_bounds__(128, 2)
void gemm_mma(const __nv_bfloat16* __restrict__ Ah, const __nv_bfloat16* __restrict__ Al,
              const __nv_bfloat16* __restrict__ Bh, const __nv_bfloat16* __restrict__ Bl,
              const float* __restrict__ bias, const float* __restrict__ Res,
              float* __restrict__ Cf, __nv_bfloat16* __restrict__ Chi, __nv_bfloat16* __restrict__ Clo,
              int K, int lda, int ldb, int ldc,
              float alpha)
{
    constexpr int LDS = 40;
    constexpr int A_H = 128 * LDS;
    constexpr int B_H = 128 * LDS;
    constexpr int STG = 2 * A_H + 2 * B_H;

    extern __shared__ __align__(16) __nv_bfloat16 sm[];
    const uint32_t sb = su32(sm);

    const int tid = threadIdx.x, wid = tid >> 5, lane = tid & 31;
    const int wm = wid >> 1, wn = wid & 1;
    const int bmat = lane >> 3, bmr = lane & 7;

    const int mBlk = blockIdx.y * 128, nBlk = blockIdx.x * 128;
    Ah += (long)mBlk * lda; Al += (long)mBlk * lda;
    Bh += (long)nBlk * ldb; Bl += (long)nBlk * ldb;

    auto stage_copy = [&](int t, int s) {
        const int kt = t * 32;
        const uint32_t st = sb + 2u * (uint32_t)(s * STG);
        #pragma unroll
        for (int j = 0; j < 4; j++) {
            const int i = tid + j * 128;
            const int r = i >> 2, cg = (i & 3) * 8;
            const long goA = (long)r * lda + kt + cg;
            const uint32_t dA = st + 2u * (uint32_t)(r * LDS + cg);
            cpa16(dA,            Ah + goA);
            cpa16(dA + 2u * A_H, Al + goA);
            const long goB = (long)r * ldb + kt + cg;
            const uint32_t dB = st + 2u * (uint32_t)(2 * A_H + r * LDS + cg);
            cpa16(dB,            Bh + goB);
            cpa16(dB + 2u * B_H, Bl + goB);
        }
        cp_commit();
    };

    float acc[4][8][4];
    #pragma unroll
    for (int i = 0; i < 4; i++)
        #pragma unroll
        for (int j = 0; j < 8; j++)
            #pragma unroll
            for (int q = 0; q < 4; q++) acc[i][j][q] = 0.f;

    const int nt = K / 32;
    stage_copy(0, 0);

    for (int t = 0; t < nt; t++) {
        if (t + 1 < nt) stage_copy(t + 1, (t + 1) & 1);
        if (t + 1 < nt) asm volatile("cp.async.wait_group 1;" ::: "memory");
        else            asm volatile("cp.async.wait_group 0;" ::: "memory");
        __syncthreads();

        const int s = t & 1;
        const uint32_t ab = sb + 2u * (uint32_t)(s * STG);
        const uint32_t bb = ab + 2u * (uint32_t)(2 * A_H);

        #pragma unroll
        for (int ks = 0; ks < 2; ks++) {
            const int acol = ks * 16 + (lane >> 4) * 8;
            uint32_t afh[4][4], afl[4][4];
            #pragma unroll
            for (int mt = 0; mt < 4; mt++) {
                const uint32_t ad = ab + 2u * (uint32_t)((wm * 64 + mt * 16 + (lane & 15)) * LDS + acol);
                ldm4(afh[mt], ad);
                ldm4(afl[mt], ad + 2u * A_H);
            }
            uint32_t bfh[16], bfl[16];
            #pragma unroll
            for (int p = 0; p < 4; p++) {
                const int n = wn * 64 + (p * 2 + (bmat >> 1)) * 8 + bmr;
                const int koff = ks * 16 + (bmat & 1) * 8;
                const uint32_t bd = bb + 2u * (uint32_t)(n * LDS + koff);
                ldm4(&bfh[p * 4], bd);
                ldm4(&bfl[p * 4], bd + 2u * B_H);
            }
            #pragma unroll
            for (int mt = 0; mt < 4; mt++) {
                #pragma unroll
                for (int n4 = 0; n4 < 8; n4++) {
                    const int bi = (n4 >> 1) * 4 + (n4 & 1) * 2;
                    mma16816(acc[mt][n4], afh[mt], bfh[bi], bfh[bi + 1]);
                    mma16816(acc[mt][n4], afh[mt], bfl[bi], bfl[bi + 1]);
                    mma16816(acc[mt][n4], afl[mt], bfh[bi], bfh[bi + 1]);
                }
            }
        }
        __syncthreads();
    }

    const int mW = mBlk + wm * 64;
    const int nW = nBlk + wn * 64;
    #pragma unroll
    for (int mt = 0; mt < 4; mt++) {
        #pragma unroll
        for (int n4 = 0; n4 < 8; n4++) {
            const int n0 = nW + n4 * 8 + (lane & 3) * 2;
            float bx = 0.f, by = 0.f;
            if (bias) { bx = bias[n0]; by = bias[n0 + 1]; }
            #pragma unroll
            for (int half = 0; half < 2; half++) {
                const int m = mW + mt * 16 + half * 8 + (lane >> 2);
                float v0 = acc[mt][n4][half * 2 + 0] + bx;
                float v1 = acc[mt][n4][half * 2 + 1] + by;
                v0 *= alpha; v1 *= alpha;
                if (RELU) { v0 = fmaxf(v0, 0.f); v1 = fmaxf(v1, 0.f); }
                if (MODE == 0) {
                    const long ro = (long)m * ldc + n0;
                    if (Res) { v0 += Res[ro]; v1 += Res[ro + 1]; }
                    *reinterpret_cast<float2*>(Cf + ro) = make_float2(v0, v1);
                } else if (MODE == 1) {
                    const long ro = (long)m * ldc + n0;
                    __nv_bfloat16 h0, h1, l0, l1;
                    split2(v0, h0, l0); split2(v1, h1, l1);
                    *reinterpret_cast<uint32_t*>(Chi + ro) = pack2(h0, h1);
                    *reinterpret_cast<uint32_t*>(Clo + ro) = pack2(l0, l1);
                } else {   // MODE 2: vt[(b*512 + n)*512 + t]
                    const int bq = m >> 9, tq = m & 511;
                    __nv_bfloat16 h0, h1, l0, l1;
                    split2(v0, h0, l0); split2(v1, h1, l1);
                    const long a0 = ((long)(bq * 512 + n0)) * 512 + tq;
                    const long a1 = a0 + 512;
                    Chi[a0] = h0; Clo[a0] = l0;
                    Chi[a1] = h1; Clo[a1] = l1;
                }
            }
        }
    }
}

// ---------------- fused flash attention (unchanged from passing R10) -----------
__global__ __launch_bounds__(512, 1)
void flash_attn(const __nv_bfloat16* __restrict__ Qh, const __nv_bfloat16* __restrict__ Ql,
                const __nv_bfloat16* __restrict__ Kh, const __nv_bfloat16* __restrict__ Kl,
                const __nv_bfloat16* __restrict__ Vh, const __nv_bfloat16* __restrict__ Vl,
                __nv_bfloat16* __restrict__ Ch, __nv_bfloat16* __restrict__ Cl)
{
    constexpr int oQH = 0,      oQL = 18432;
    constexpr int oKH = 36864,  oKL = 55296;
    constexpr int oVH = 73728,  oVL = 91136;
    constexpr int oPH = 108544, oPL = 143360;
    constexpr int oPM = 178176, oPS = 180224;
    constexpr int oM  = 182272, oL = 182784, oS = 183296;
    extern __shared__ __align__(16) char smf[];
    const uint32_t sb = su32(smf);
    float* pm   = reinterpret_cast<float*>(smf + oPM);
    float* ps   = reinterpret_cast<float*>(smf + oPS);
    float* mrow = reinterpret_cast<float*>(smf + oM);
    float* lrow = reinterpret_cast<float*>(smf + oL);
    float* srow = reinterpret_cast<float*>(smf + oS);

    const int tid = threadIdx.x, wid = tid >> 5, lane = tid & 31;
    const int wm = wid >> 2, wn = wid & 3;
    const int om = wid >> 1, on = wid & 1;
    const int qt = blockIdx.x, z = blockIdx.y;
    const int b = z >> 3, h = z & 7;
    const int bmat = lane >> 3, bmr = lane & 7;

    {
        const long base = (long)(b * 512 + qt * 128) * 512 + h * 64;
        for (int i = tid; i < 1024; i += 512) {
            const int r = i >> 3, c8 = (i & 7) * 8;
            const long go = base + (long)r * 512 + c8;
            *reinterpret_cast<uint4*>(smf + oQH + 2 * (r * 72 + c8)) =
                *reinterpret_cast<const uint4*>(Qh + go);
            *reinterpret_cast<uint4*>(smf + oQL + 2 * (r * 72 + c8)) =
                *reinterpret_cast<const uint4*>(Ql + go);
        }
    }
    if (tid < 128) { mrow[tid] = -1e30f; lrow[tid] = 0.f; }

    float acc_o[4][4];
    #pragma unroll
    for (int i = 0; i < 4; i++)
        #pragma unroll
        for (int j = 0; j < 4; j++) acc_o[i][j] = 0.f;

    __syncthreads();

    for (int kb = 0; kb < 4; kb++) {
        {
            const long kbase = (long)(b * 512 + kb * 128) * 512 + h * 64;
            for (int i = tid; i < 1024; i += 512) {
                const int r = i >> 3, c8 = (i & 7) * 8;
                const long go = kbase + (long)r * 512 + c8;
                *reinterpret_cast<uint4*>(smf + oKH + 2 * (r * 72 + c8)) =
                    *reinterpret_cast<const uint4*>(Kh + go);
                *reinterpret_cast<uint4*>(smf + oKL + 2 * (r * 72 + c8)) =
                    *reinterpret_cast<const uint4*>(Kl + go);
            }
            const long vbase = (long)(b * 512 + h * 64) * 512 + kb * 128;
            for (int i = tid; i < 1024; i += 512) {
                const int r = i >> 4, c8 = (i & 15) * 8;
                const long go = vbase + (long)r * 512 + c8;
                *reinterpret_cast<uint4*>(smf + oVH + 2 * (r * 136 + c8)) =
                    *reinterpret_cast<const uint4*>(Vh + go);
                *reinterpret_cast<uint4*>(smf + oVL + 2 * (r * 136 + c8)) =
                    *reinterpret_cast<const uint4*>(Vl + go);
            }
        }
        __syncthreads();

        float acc_s[2][4][4];
        #pragma unroll
        for (int i = 0; i < 2; i++)
            #pragma unroll
            for (int j = 0; j < 4; j++)
                #pragma unroll
                for (int q = 0; q < 4; q++) acc_s[i][j][q] = 0.f;

        #pragma unroll
        for (int ks = 0; ks < 4; ks++) {
            const int acol = ks * 16 + (lane >> 4) * 8;
            uint32_t afh[2][4], afl[2][4];
            #pragma unroll
            for (int mt = 0; mt < 2; mt++) {
                const uint32_t ad = sb + oQH +
                    2u * (uint32_t)((wm * 32 + mt * 16 + (lane & 15)) * 72 + acol);
                ldm4(afh[mt], ad);
                ldm4(afl[mt], ad + (oQL - oQH));
            }
            uint32_t bfh[8], bfl[8];
            #pragma unroll
            for (int p = 0; p < 2; p++) {
                const int n = wn * 32 + (p * 2 + (bmat >> 1)) * 8 + bmr;
                const int koff = ks * 16 + (bmat & 1) * 8;
                const uint32_t bd = sb + oKH + 2u * (uint32_t)(n * 72 + koff);
                ldm4(&bfh[p * 4], bd);
                ldm4(&bfl[p * 4], bd + (oKL - oKH));
            }
            #pragma unroll
            for (int mt = 0; mt < 2; mt++) {
                #pragma unroll
                for (int n4 = 0; n4 < 4; n4++) {
                    const int bi = (n4 >> 1) * 4 + (n4 & 1) * 2;
                    mma16816(acc_s[mt][n4], afh[mt], bfh[bi], bfh[bi + 1]);
                    mma16816(acc_s[mt][n4], afh[mt], bfl[bi], bfl[bi + 1]);
                    mma16816(acc_s[mt][n4], afl[mt], bfh[bi], bfh[bi + 1]);
                }
            }
        }

        #pragma unroll
        for (int mt = 0; mt < 2; mt++) {
            #pragma unroll
            for (int half = 0; half < 2; half++) {
                float vmax = -1e30f;
                #pragma unroll
                for (int n4 = 0; n4 < 4; n4++)
                    vmax = fmaxf(vmax, fmaxf(acc_s[mt][n4][half * 2], acc_s[mt][n4][half * 2 + 1]));
                vmax = fmaxf(vmax, __shfl_xor_sync(0xffffffffu, vmax, 1));
                vmax = fmaxf(vmax, __shfl_xor_sync(0xffffffffu, vmax, 2));
                if ((lane & 3) == 0) {
                    const int row = wm * 32 + mt * 16 + half * 8 + (lane >> 2);
                    pm[row * 4 + wn] = vmax;
                }
            }
        }
        __syncthreads();
        if (tid < 128) {
            const float mb = fmaxf(fmaxf(pm[tid * 4], pm[tid * 4 + 1]),
                                   fmaxf(pm[tid * 4 + 2], pm[tid * 4 + 3]));
            const float mn = fmaxf(mrow[tid], mb);
            srow[tid] = __expf(mrow[tid] - mn);
            mrow[tid] = mn;
        }
        __syncthreads();

        #pragma unroll
        for (int mt = 0; mt < 2; mt++) {
            #pragma unroll
            for (int half = 0; half < 2; half++) {
                const int row = wm * 32 + mt * 16 + half * 8 + (lane >> 2);
                const float mi = mrow[row];
                float rs = 0.f;
                #pragma unroll
                for (int n4 = 0; n4 < 4; n4++) {
                    const float p0 = __expf(acc_s[mt][n4][half * 2 + 0] - mi);
                    const float p1 = __expf(acc_s[mt][n4][half * 2 + 1] - mi);
                    rs += p0 + p1;
                    const int col = wn * 32 + n4 * 8 + (lane & 3) * 2;
                    __nv_bfloat16 h0, h1, l0, l1;
                    split2(p0, h0, l0); split2(p1, h1, l1);
                    *reinterpret_cast<uint32_t*>(smf + oPH + 2 * (row * 136 + col)) = pack2(h0, h1);
                    *reinterpret_cast<uint32_t*>(smf + oPL + 2 * (row * 136 + col)) = pack2(l0, l1);
                }
                rs += __shfl_xor_sync(0xffffffffu, rs, 1);
                rs += __shfl_xor_sync(0xffffffffu, rs, 2);
                if ((lane & 3) == 0) ps[row * 4 + wn] = rs;
            }
        }
        __syncthreads();

        if (tid < 128)
            lrow[tid] = lrow[tid] * srow[tid] +
                        (ps[tid * 4] + ps[tid * 4 + 1] + ps[tid * 4 + 2] + ps[tid * 4 + 3]);

        {
            const int r0 = om * 16 + (lane >> 2);
            const float s0 = srow[r0], s1 = srow[r0 + 8];
            #pragma unroll
            for (int n4 = 0; n4 < 4; n4++) {
                acc_o[n4][0] *= s0; acc_o[n4][1] *= s0;
                acc_o[n4][2] *= s1; acc_o[n4][3] *= s1;
            }
        }

        #pragma unroll
        for (int ks2 = 0; ks2 < 8; ks2++) {
            const int acol = ks2 * 16 + (lane >> 4) * 8;
            uint32_t pah[4], pal[4];
            {
                const uint32_t ad = sb + oPH +
                    2u * (uint32_t)((om * 16 + (lane & 15)) * 136 + acol);
                ldm4(pah, ad);
                ldm4(pal, ad + (oPL - oPH));
            }
            uint32_t bfh[8], bfl[8];
            #pragma unroll
            for (int p = 0; p < 2; p++) {
                const int n = on * 32 + (p * 2 + (bmat >> 1)) * 8 + bmr;
                const int koff = ks2 * 16 + (bmat & 1) * 8;
                const uint32_t bd = sb + oVH + 2u * (uint32_t)(n * 136 + koff);
                ldm4(&bfh[p * 4], bd);
                ldm4(&bfl[p * 4], bd + (oVL - oVH));
            }
            #pragma unroll
            for (int n4 = 0; n4 < 4; n4++) {
                const int bi = (n4 >> 1) * 4 + (n4 & 1) * 2;
                mma16816(acc_o[n4], pah, bfh[bi], bfh[bi + 1]);
                mma16816(acc_o[n4], pah, bfl[bi], bfl[bi + 1]);
                mma16816(acc_o[n4], pal, bfh[bi], bfh[bi + 1]);
            }
        }
        __syncthreads();
    }

    if (tid < 128) srow[tid] = 1.f / lrow[tid];
    __syncthreads();
    {
        const int r0 = om * 16 + (lane >> 2);
        const float i0 = srow[r0], i1 = srow[r0 + 8];
        const long gq = (long)(b * 512 + qt * 128);
        #pragma unroll
        for (int n4 = 0; n4 < 4; n4++) {
            const int c0 = on * 32 + n4 * 8 + (lane & 3) * 2;
            const float v00 = acc_o[n4][0] * i0, v01 = acc_o[n4][1] * i0;
            const float v10 = acc_o[n4][2] * i1, v11 = acc_o[n4][3] * i1;
            const long a0 = (gq + r0) * 512 + h * 64 + c0;
            const long a1 = (gq + r0 + 8) * 512 + h * 64 + c0;
            __nv_bfloat16 h0, h1, l0, l1;
            split2(v00, h0, l0); split2(v01, h1, l1);
            *reinterpret_cast<uint32_t*>(Ch + a0) = pack2(h0, h1);
            *reinterpret_cast<uint32_t*>(Cl + a0) = pack2(l0, l1);
            split2(v10, h0, l0); split2(v11, h1, l1);
            *reinterpret_cast<uint32_t*>(Ch + a1) = pack2(h0, h1);
            *reinterpret_cast<uint32_t*>(Cl + a1) = pack2(l0, l1);
        }
    }
}

// ---------------- merged fp32 -> bf16 hi/lo split (all 8 tensors, 1 launch) ----
// float4-unit boundaries (cumulative)
constexpr long C_X  = 2097152;           // x      [16384,512]
constexpr long C_WQ = C_X  + 65536;
constexpr long C_WK = C_WQ + 65536;
constexpr long C_WV = C_WK + 65536;
constexpr long C_WO = C_WV + 65536;
constexpr long C_W1 = C_WO + 32768;      // W1 pad [256,512], src [200,512]
constexpr long C_W2 = C_W1 + 16384;      // W2 pad [256,256], src [200,200]
constexpr long C_W3 = C_W2 + 32768;      // W3 pad [512,256], src [512,200]
// grid = C_W3 / 256 = 9536

__global__ __launch_bounds__(256)
void split_all(unsigned char* __restrict__ ar,
               const float* __restrict__ x,  const float* __restrict__ Wq,
               const float* __restrict__ Wk, const float* __restrict__ Wv,
               const float* __restrict__ Wo, const float* __restrict__ W1,
               const float* __restrict__ W2, const float* __restrict__ W3)
{
    const long i4 = (long)blockIdx.x * 256 + threadIdx.x;
    const float* src; size_t oh, ol; long l4; int rs = 0, cs = 0, cd = 0;
    if      (i4 < C_X)  { src = x;  oh = O_XH;  ol = O_XL;  l4 = i4; }
    else if (i4 < C_WQ) { src = Wq; oh = O_WQH; ol = O_WQL; l4 = i4 - C_X; }
    else if (i4 < C_WK) { src = Wk; oh = O_WKH; ol = O_WKL; l4 = i4 - C_WQ; }
    else if (i4 < C_WV) { src = Wv; oh = O_WVH; ol = O_WVL; l4 = i4 - C_WK; }
    else if (i4 < C_WO) { src = Wo; oh = O_WOH; ol = O_WOL; l4 = i4 - C_WV; }
    else if (i4 < C_W1) { src = W1; oh = O_W1H; ol = O_W1L; l4 = i4 - C_WO; rs = 200; cs = 512; cd = 512; }
    else if (i4 < C_W2) { src = W2; oh = O_W2H; ol = O_W2L; l4 = i4 - C_W1; rs = 200; cs = 200; cd = 256; }
    else                { src = W3; oh = O_W3H; ol = O_W3L; l4 = i4 - C_W2; rs = 512; cs = 200; cd = 256; }

    const long e = l4 * 4;
    float4 v = make_float4(0.f, 0.f, 0.f, 0.f);
    if (rs == 0) {
        v = *reinterpret_cast<const float4*>(src + e);
    } else {
        const int r = (int)(e / cd), c = (int)(e % cd);
        if (r < rs && c < cs)
            v = *reinterpret_cast<const float4*>(src + (long)r * cs + c);
    }
    __nv_bfloat16 h0, h1, h2, h3, l0, l1, l2, l3;
    split2(v.x, h0, l0); split2(v.y, h1, l1); split2(v.z, h2, l2); split2(v.w, h3, l3);
    *reinterpret_cast<uint2*>(reinterpret_cast<__nv_bfloat16*>(ar + oh) + e) =
        make_uint2(pack2(h0, h1), pack2(h2, h3));
    *reinterpret_cast<uint2*>(reinterpret_cast<__nv_bfloat16*>(ar + ol) + e) =
        make_uint2(pack2(l0, l1), pack2(l2, l3));
}

__global__ void pad_bias2(const float* __restrict__ s1, float* __restrict__ d1,
                          const float* __restrict__ s2, float* __restrict__ d2, int n) {
    const int i = threadIdx.x;
    if (blockIdx.x == 0) d1[i] = (i < n) ? s1[i] : 0.f;
    else                 d2[i] = (i < n) ? s2[i] : 0.f;
}

// ---------------- 2-D LayerNorm over (S,D) per batch (R10 monolithic) ----------
template<bool PAIR>
__global__ __launch_bounds__(1024)
void layernorm_kernel(const float* __restrict__ X,
                      const float* __restrict__ gamma, const float* __restrict__ beta,
                      float* __restrict__ out, __nv_bfloat16* __restrict__ oh,
                      __nv_bfloat16* __restrict__ ol)
{
    const long base = (long)blockIdx.x * LN_N;
    float s1 = 0.f, s2 = 0.f;
    for (int i = threadIdx.x * 4; i < LN_N; i += 4096) {
        float4 v = *reinterpret_cast<const float4*>(X + base + i);
        s1 += (v.x + v.y) + (v.z + v.w);
        s2 += (v.x*v.x + v.y*v.y) + (v.z*v.z + v.w*v.w);
    }
    __shared__ float r1[32], r2[32];
    const int lane = threadIdx.x & 31, wid = threadIdx.x >> 5;
    #pragma unroll
    for (int o = 16; o; o >>= 1) {
        s1 += __shfl_xor_sync(0xffffffffu, s1, o);
        s2 += __shfl_xor_sync(0xffffffffu, s2, o);
    }
    if (!lane) { r1[wid] = s1; r2[wid] = s2; }
    __syncthreads();
    if (threadIdx.x < 32) {
        s1 = r1[threadIdx.x]; s2 = r2[threadIdx.x];
        #pragma unroll
        for (int o = 16; o; o >>= 1) {
            s1 += __shfl_xor_sync(0xffffffffu, s1, o);
            s2 += __shfl_xor_sync(0xffffffffu, s2, o);
        }
        if (!threadIdx.x) { r1[0] = s1; r2[0] = s2; }
    }
    __syncthreads();
    const float mean = r1[0] / (float)LN_N;
    const float var  = r2[0] / (float)LN_N - mean * mean;
    const float rstd = rsqrtf(var + 1e-5f);

    for (int i = threadIdx.x * 4; i < LN_N; i += 4096) {
        float4 v = *reinterpret_cast<const float4*>(X + base + i);
        float4 g  = *reinterpret_cast<const float4*>(gamma + i);
        float4 bt = *reinterpret_cast<const float4*>(beta  + i);
        float4 o;
        o.x = (v.x - mean) * rstd * g.x + bt.x;
        o.y = (v.y - mean) * rstd * g.y + bt.y;
        o.z = (v.z - mean) * rstd * g.z + bt.z;
        o.w = (v.w - mean) * rstd * g.w + bt.w;
        *reinterpret_cast<float4*>(out + base + i) = o;
        if (PAIR) {
            __nv_bfloat16 h0, h1, h2, h3, l0, l1, l2, l3;
            split2(o.x, h0, l0); split2(o.y, h1, l1); split2(o.z, h2, l2); split2(o.w, h3, l3);
            *reinterpret_cast<uint2*>(oh + base + i) = make_uint2(pack2(h0, h1), pack2(h2, h3));
            *reinterpret_cast<uint2*>(ol + base + i) = make_uint2(pack2(l0, l1), pack2(l2, l3));
        }
    }
}

// ---------------- launch --------------------------------------------------------
extern "C" void kernel_launch(void* const* d_in, const int* in_sizes, int n_in,
                              void* d_out, int out_size)
{
    const float* x  = (const float*)d_in[0];
    const float* Wq = (const float*)d_in[1];
    const float* bq = (const float*)d_in[2];
    const float* Wk = (const float*)d_in[3];
    const float* bk = (const float*)d_in[4];
    const float* Wv = (const float*)d_in[5];
    const float* bv = (const float*)d_in[6];
    const float* Wo = (const float*)d_in[7];
    const float* bo = (const float*)d_in[8];
    const float* W1 = (const float*)d_in[9];
    const float* b1 = (const float*)d_in[10];
    const float* W2 = (const float*)d_in[11];
    const float* b2 = (const float*)d_in[12];
    const float* W3 = (const float*)d_in[13];
    const float* b3 = (const float*)d_in[14];
    const float* gamma = (const float*)d_in[15];
    const float* beta  = (const float*)d_in[16];
    float* out = (float*)d_out;

    unsigned char* ar;
    cudaGetSymbolAddress((void**)&ar, g_arena);
    #define BF(o) reinterpret_cast<__nv_bfloat16*>(ar + (o))
    #define FP(o) reinterpret_cast<float*>(ar + (o))

    const int SMG  = 2 * (2 * 128 * 40 + 2 * 128 * 40) * 2;   // 81920
    const int SMFL = 183808;
    cudaFuncSetAttribute((const void*)gemm_mma<0, false>, cudaFuncAttributeMaxDynamicSharedMemorySize, SMG);
    cudaFuncSetAttribute((const void*)gemm_mma<1, false>, cudaFuncAttributeMaxDynamicSharedMemorySize, SMG);
    cudaFuncSetAttribute((const void*)gemm_mma<1, true >, cudaFuncAttributeMaxDynamicSharedMemorySize, SMG);
    cudaFuncSetAttribute((const void*)gemm_mma<2, false>, cudaFuncAttributeMaxDynamicSharedMemorySize, SMG);
    cudaFuncSetAttribute((const void*)flash_attn, cudaFuncAttributeMaxDynamicSharedMemorySize, SMFL);

    // ---- merged splits (one full-chip launch) + bias pads ----
    split_all<<<(unsigned)(C_W3 / 256), 256>>>(ar, x, Wq, Wk, Wv, Wo, W1, W2, W3);
    pad_bias2<<<2, 256>>>(b1, FP(O_B1P), b2, FP(O_B2P), NFF);

    // ---- 1) Q/K/V projections (q pre-scaled by 1/8; v written transposed) ----
    {
        dim3 grid(4, 128, 1);
        gemm_mma<1, false><<<grid, 128, SMG>>>(
            BF(O_XH), BF(O_XL), BF(O_WQH), BF(O_WQL), bq, nullptr,
            nullptr, BF(O_QH), BF(O_QL), ND, ND, ND, ND, 0.125f);
        gemm_mma<1, false><<<grid, 128, SMG>>>(
            BF(O_XH), BF(O_XL), BF(O_WKH), BF(O_WKL), bk, nullptr,
            nullptr, BF(O_KH), BF(O_KL), ND, ND, ND, ND, 1.f);
        gemm_mma<2, false><<<grid, 128, SMG>>>(
            BF(O_XH), BF(O_XL), BF(O_WVH), BF(O_WVL), bv, nullptr,
            nullptr, BF(O_VTH), BF(O_VTL), ND, ND, ND, ND, 1.f);
    }

    // ---- 2-4) fused flash attention -> concat pairs ----
    {
        dim3 grid(4, NB * NH);
        flash_attn<<<grid, 512, SMFL>>>(
            BF(O_QH), BF(O_QL), BF(O_KH), BF(O_KL),
            BF(O_VTH), BF(O_VTL), BF(O_CCH), BF(O_CCL));
    }

    // ---- 5) y = concat @ Wo^T + bo + x  (fp32) ----
    {
        dim3 grid(4, 128, 1);
        gemm_mma<0, false><<<grid, 128, SMG>>>(
            BF(O_CCH), BF(O_CCL), BF(O_WOH), BF(O_WOL), bo, x,
            FP(O_Y), nullptr, nullptr, ND, ND, ND, ND, 1.f);
    }

    // ---- 6) y = LN(y), also emit bf16 pair ----
    layernorm_kernel<true><<<NB, 1024>>>(FP(O_Y), gamma, beta,
                                         FP(O_Y), BF(O_YH), BF(O_YL));

    // ---- 7) f1 = relu(y @ W1p^T + b1p) pair, N=256 ----
    {
        dim3 grid(2, 128, 1);
        gemm_mma<1, true><<<grid, 128, SMG>>>(
            BF(O_YH), BF(O_YL), BF(O_W1H), BF(O_W1L), FP(O_B1P), nullptr,
            nullptr, BF(O_F1H), BF(O_F1L), ND, ND, ND, NFP, 1.f);
    }
    // ---- 8) f2 = relu(f1 @ W2p^T + b2p) pair, K=N=256 ----
    {
        dim3 grid(2, 128, 1);
        gemm_mma<1, true><<<grid, 128, SMG>>>(
            BF(O_F1H), BF(O_F1L), BF(O_W2H), BF(O_W2L), FP(O_B2P), nullptr,
            nullptr, BF(O_F2H), BF(O_F2L), NFP, NFP, NFP, NFP, 1.f);
    }
    // ---- 9) f3 = f2 @ W3p^T + b3 + y  (fp32, residual folded) ----
    {
        dim3 grid(4, 128, 1);
        gemm_mma<0, false><<<grid, 128, SMG>>>(
            BF(O_F2H), BF(O_F2L), BF(O_W3H), BF(O_W3L), b3, FP(O_Y),
            FP(O_F3), nullptr, nullptr, NFP, NFP, NFP, ND, 1.f);
    }

    // ---- 10) y2 = LN(f3)  (f3 already includes +y) ----
    layernorm_kernel<false><<<NB, 1024>>>(FP(O_F3), gamma, beta,
                                          FP(O_Y2), nullptr, nullptr);
    // ---- 11) out = LN(y2) ----
    layernorm_kernel<false><<<NB, 1024>>>(FP(O_Y2), gamma, beta,
                                          out, nullptr, nullptr);
}

// round 13
// speedup vs baseline: 1.4070x; 1.0276x over previous
#include <cuda_runtime.h>
#include <cuda_bf16.h>
#include <cstdint>

// ---------------- problem dims ------------------------------------------------
#define NB   32
#define NS   512
#define ND   512
#define NH   8
#define NDK  64
#define NFF  200
#define NFP  256            // padded FF width
#define NM   (NB * NS)      // 16384 rows
#define LN_N (NS * ND)      // 262144 elems per batch for 2-D LayerNorm

// ---------------- arena (single static device allocation) ---------------------
constexpr size_t SZ_BF_MD = (size_t)NM * ND * 2;        // [16384,512] bf16
constexpr size_t SZ_BF_DD = (size_t)ND * ND * 2;        // [512,512]  bf16
constexpr size_t SZ_BF_W1 = (size_t)NFP * ND * 2;
constexpr size_t SZ_BF_W2 = (size_t)NFP * NFP * 2;
constexpr size_t SZ_BF_W3 = (size_t)ND * NFP * 2;
constexpr size_t SZ_F_MD  = (size_t)NM * ND * 4;
constexpr size_t SZ_BF_MF = (size_t)NM * NFP * 2;

constexpr size_t O_XH = 0,                 O_XL = O_XH + SZ_BF_MD;
constexpr size_t O_WQH = O_XL + SZ_BF_MD,  O_WQL = O_WQH + SZ_BF_DD;
constexpr size_t O_WKH = O_WQL + SZ_BF_DD, O_WKL = O_WKH + SZ_BF_DD;
constexpr size_t O_WVH = O_WKL + SZ_BF_DD, O_WVL = O_WVH + SZ_BF_DD;
constexpr size_t O_WOH = O_WVL + SZ_BF_DD, O_WOL = O_WOH + SZ_BF_DD;
constexpr size_t O_W1H = O_WOL + SZ_BF_DD, O_W1L = O_W1H + SZ_BF_W1;
constexpr size_t O_W2H = O_W1L + SZ_BF_W1, O_W2L = O_W2H + SZ_BF_W2;
constexpr size_t O_W3H = O_W2L + SZ_BF_W2, O_W3L = O_W3H + SZ_BF_W3;
constexpr size_t O_B1P = O_W3L + SZ_BF_W3, O_B2P = O_B1P + 1024;
constexpr size_t O_QH  = O_B2P + 1024,     O_QL  = O_QH + SZ_BF_MD;
constexpr size_t O_KH  = O_QL + SZ_BF_MD,  O_KL  = O_KH + SZ_BF_MD;
constexpr size_t O_VTH = O_KL + SZ_BF_MD,  O_VTL = O_VTH + SZ_BF_MD;
constexpr size_t O_CCH = O_VTL + SZ_BF_MD, O_CCL = O_CCH + SZ_BF_MD;
constexpr size_t O_Y   = O_CCL + SZ_BF_MD;
constexpr size_t O_YH  = O_Y + SZ_F_MD,    O_YL  = O_YH + SZ_BF_MD;
constexpr size_t O_F1H = O_YL + SZ_BF_MD,  O_F1L = O_F1H + SZ_BF_MF;
constexpr size_t O_F2H = O_F1L + SZ_BF_MF, O_F2L = O_F2H + SZ_BF_MF;
constexpr size_t O_F3  = O_F2L + SZ_BF_MF;
constexpr size_t O_Y2  = O_F3 + SZ_F_MD;
constexpr size_t ARENA = O_Y2 + SZ_F_MD;

__device__ __align__(1024) unsigned char g_arena[ARENA];

// ---------------- helpers -----------------------------------------------------
__device__ __forceinline__ uint32_t su32(const void* p) {
    uint32_t a;
    asm("{ .reg .u64 t; cvta.to.shared.u64 t, %1; cvt.u32.u64 %0, t; }" : "=r"(a) : "l"(p));
    return a;
}
__device__ __forceinline__ void cpa16(uint32_t d, const void* s) {
    asm volatile("cp.async.ca.shared.global [%0], [%1], 16;" :: "r"(d), "l"(s));
}
__device__ __forceinline__ void cp_commit() {
    asm volatile("cp.async.commit_group;" ::: "memory");
}
__device__ __forceinline__ void ldm4(uint32_t* r, uint32_t a) {
    asm volatile("ldmatrix.sync.aligned.m8n8.x4.shared.b16 {%0,%1,%2,%3}, [%4];"
        : "=r"(r[0]), "=r"(r[1]), "=r"(r[2]), "=r"(r[3]) : "r"(a));
}
__device__ __forceinline__ void mma16816(float* c, const uint32_t* a, uint32_t b0, uint32_t b1) {
    asm volatile("mma.sync.aligned.m16n8k16.row.col.f32.bf16.bf16.f32 "
        "{%0,%1,%2,%3}, {%4,%5,%6,%7}, {%8,%9}, {%0,%1,%2,%3};"
        : "+f"(c[0]), "+f"(c[1]), "+f"(c[2]), "+f"(c[3])
        : "r"(a[0]), "r"(a[1]), "r"(a[2]), "r"(a[3]), "r"(b0), "r"(b1));
}
__device__ __forceinline__ void split2(float v, __nv_bfloat16& h, __nv_bfloat16& l) {
    h = __float2bfloat16(v);
    l = __float2bfloat16(v - __bfloat162float(h));
}
__device__ __forceinline__ uint32_t pack2(__nv_bfloat16 a, __nv_bfloat16 b) {
    return (uint32_t)__bfloat16_as_ushort(a) | ((uint32_t)__bfloat16_as_ushort(b) << 16);
}

// ---------------- shared GEMM mainloop macro-parts -----------------------------
// (4 warps of 64x64, BK=32, 2-stage cp.async; B-frags loaded per p-group to
//  keep live registers low)

// ---------------- bf16 HMMA GEMM: generic (Wo/W1/W2/W3 path) -------------------
template<int MODE, bool RELU>
__global__ __launch_bounds__(128, 2)
void gemm_mma(const __nv_bfloat16* __restrict__ Ah, const __nv_bfloat16* __restrict__ Al,
              const __nv_bfloat16* __restrict__ Bh, const __nv_bfloat16* __restrict__ Bl,
              const float* __restrict__ bias, const float* __restrict__ Res,
              float* __restrict__ Cf, __nv_bfloat16* __restrict__ Chi, __nv_bfloat16* __restrict__ Clo,
              int K, int lda, int ldb, int ldc,
              float alpha)
{
    constexpr int LDS = 40;
    constexpr int A_H = 128 * LDS;
    constexpr int B_H = 128 * LDS;
    constexpr int STG = 2 * A_H + 2 * B_H;

    extern __shared__ __align__(16) __nv_bfloat16 sm[];
    const uint32_t sb = su32(sm);

    const int tid = threadIdx.x, wid = tid >> 5, lane = tid & 31;
    const int wm = wid >> 1, wn = wid & 1;
    const int bmat = lane >> 3, bmr = lane & 7;

    const int mBlk = blockIdx.y * 128, nBlk = blockIdx.x * 128;
    Ah += (long)mBlk * lda; Al += (long)mBlk * lda;
    Bh += (long)nBlk * ldb; Bl += (long)nBlk * ldb;

    auto stage_copy = [&](int t, int s) {
        const int kt = t * 32;
        const uint32_t st = sb + 2u * (uint32_t)(s * STG);
        #pragma unroll
        for (int j = 0; j < 4; j++) {
            const int i = tid + j * 128;
            const int r = i >> 2, cg = (i & 3) * 8;
            const long goA = (long)r * lda + kt + cg;
            const uint32_t dA = st + 2u * (uint32_t)(r * LDS + cg);
            cpa16(dA,            Ah + goA);
            cpa16(dA + 2u * A_H, Al + goA);
            const long goB = (long)r * ldb + kt + cg;
            const uint32_t dB = st + 2u * (uint32_t)(2 * A_H + r * LDS + cg);
            cpa16(dB,            Bh + goB);
            cpa16(dB + 2u * B_H, Bl + goB);
        }
        cp_commit();
    };

    float acc[4][8][4];
    #pragma unroll
    for (int i = 0; i < 4; i++)
        #pragma unroll
        for (int j = 0; j < 8; j++)
            #pragma unroll
            for (int q = 0; q < 4; q++) acc[i][j][q] = 0.f;

    const int nt = K / 32;
    stage_copy(0, 0);

    for (int t = 0; t < nt; t++) {
        if (t + 1 < nt) stage_copy(t + 1, (t + 1) & 1);
        if (t + 1 < nt) asm volatile("cp.async.wait_group 1;" ::: "memory");
        else            asm volatile("cp.async.wait_group 0;" ::: "memory");
        __syncthreads();

        const int s = t & 1;
        const uint32_t ab = sb + 2u * (uint32_t)(s * STG);
        const uint32_t bb = ab + 2u * (uint32_t)(2 * A_H);

        #pragma unroll
        for (int ks = 0; ks < 2; ks++) {
            const int acol = ks * 16 + (lane >> 4) * 8;
            uint32_t afh[4][4], afl[4][4];
            #pragma unroll
            for (int mt = 0; mt < 4; mt++) {
                const uint32_t ad = ab + 2u * (uint32_t)((wm * 64 + mt * 16 + (lane & 15)) * LDS + acol);
                ldm4(afh[mt], ad);
                ldm4(afl[mt], ad + 2u * A_H);
            }
            #pragma unroll
            for (int p = 0; p < 4; p++) {
                uint32_t bfh[4], bfl[4];
                const int n = wn * 64 + (p * 2 + (bmat >> 1)) * 8 + bmr;
                const int koff = ks * 16 + (bmat & 1) * 8;
                const uint32_t bd = bb + 2u * (uint32_t)(n * LDS + koff);
                ldm4(bfh, bd);
                ldm4(bfl, bd + 2u * B_H);
                #pragma unroll
                for (int mt = 0; mt < 4; mt++) {
                    mma16816(acc[mt][2*p+0], afh[mt], bfh[0], bfh[1]);
                    mma16816(acc[mt][2*p+0], afh[mt], bfl[0], bfl[1]);
                    mma16816(acc[mt][2*p+0], afl[mt], bfh[0], bfh[1]);
                    mma16816(acc[mt][2*p+1], afh[mt], bfh[2], bfh[3]);
                    mma16816(acc[mt][2*p+1], afh[mt], bfl[2], bfl[3]);
                    mma16816(acc[mt][2*p+1], afl[mt], bfh[2], bfh[3]);
                }
            }
        }
        __syncthreads();
    }

    const int mW = mBlk + wm * 64;
    const int nW = nBlk + wn * 64;
    #pragma unroll
    for (int mt = 0; mt < 4; mt++) {
        #pragma unroll
        for (int n4 = 0; n4 < 8; n4++) {
            const int n0 = nW + n4 * 8 + (lane & 3) * 2;
            float bx = 0.f, by = 0.f;
            if (bias) { bx = bias[n0]; by = bias[n0 + 1]; }
            #pragma unroll
            for (int half = 0; half < 2; half++) {
                const int m = mW + mt * 16 + half * 8 + (lane >> 2);
                float v0 = acc[mt][n4][half * 2 + 0] + bx;
                float v1 = acc[mt][n4][half * 2 + 1] + by;
                v0 *= alpha; v1 *= alpha;
                if (RELU) { v0 = fmaxf(v0, 0.f); v1 = fmaxf(v1, 0.f); }
                if (MODE == 0) {
                    const long ro = (long)m * ldc + n0;
                    if (Res) { v0 += Res[ro]; v1 += Res[ro + 1]; }
                    *reinterpret_cast<float2*>(Cf + ro) = make_float2(v0, v1);
                } else {
                    const long ro = (long)m * ldc + n0;
                    __nv_bfloat16 h0, h1, l0, l1;
                    split2(v0, h0, l0); split2(v1, h1, l1);
                    *reinterpret_cast<uint32_t*>(Chi + ro) = pack2(h0, h1);
                    *reinterpret_cast<uint32_t*>(Clo + ro) = pack2(l0, l1);
                }
            }
        }
    }
}

// ---------------- fused QKV GEMM: one launch, grid (12, 128) --------------------
// blockIdx.x: 0-3 -> Q (alpha 1/8), 4-7 -> K, 8-11 -> V (transposed layout)
__global__ __launch_bounds__(128, 2)
void qkv_mma(const __nv_bfloat16* __restrict__ Ah, const __nv_bfloat16* __restrict__ Al,
             const __nv_bfloat16* __restrict__ WQh, const __nv_bfloat16* __restrict__ WQl,
             const __nv_bfloat16* __restrict__ WKh, const __nv_bfloat16* __restrict__ WKl,
             const __nv_bfloat16* __restrict__ WVh, const __nv_bfloat16* __restrict__ WVl,
             const float* __restrict__ bq, const float* __restrict__ bk, const float* __restrict__ bv,
             __nv_bfloat16* __restrict__ Qh, __nv_bfloat16* __restrict__ Ql,
             __nv_bfloat16* __restrict__ Kh, __nv_bfloat16* __restrict__ Kl,
             __nv_bfloat16* __restrict__ Vth, __nv_bfloat16* __restrict__ Vtl)
{
    constexpr int LDS = 40;
    constexpr int A_H = 128 * LDS;
    constexpr int B_H = 128 * LDS;
    constexpr int STG = 2 * A_H + 2 * B_H;
    constexpr int K = ND, lda = ND, ldb = ND;

    extern __shared__ __align__(16) __nv_bfloat16 sm[];
    const uint32_t sb = su32(sm);

    const int tid = threadIdx.x, wid = tid >> 5, lane = tid & 31;
    const int wm = wid >> 1, wn = wid & 1;
    const int bmat = lane >> 3, bmr = lane & 7;

    const int which = blockIdx.x >> 2;              // 0=q, 1=k, 2=v
    const int nBlk  = (blockIdx.x & 3) * 128;
    const int mBlk  = blockIdx.y * 128;

    const __nv_bfloat16* Bh = (which == 0) ? WQh : (which == 1) ? WKh : WVh;
    const __nv_bfloat16* Bl = (which == 0) ? WQl : (which == 1) ? WKl : WVl;
    const float* bias = (which == 0) ? bq : (which == 1) ? bk : bv;
    const float alpha = (which == 0) ? 0.125f : 1.f;
    __nv_bfloat16* Chi = (which == 0) ? Qh : (which == 1) ? Kh : Vth;
    __nv_bfloat16* Clo = (which == 0) ? Ql : (which == 1) ? Kl : Vtl;

    Ah += (long)mBlk * lda; Al += (long)mBlk * lda;
    Bh += (long)nBlk * ldb; Bl += (long)nBlk * ldb;

    auto stage_copy = [&](int t, int s) {
        const int kt = t * 32;
        const uint32_t st = sb + 2u * (uint32_t)(s * STG);
        #pragma unroll
        for (int j = 0; j < 4; j++) {
            const int i = tid + j * 128;
            const int r = i >> 2, cg = (i & 3) * 8;
            const long goA = (long)r * lda + kt + cg;
            const uint32_t dA = st + 2u * (uint32_t)(r * LDS + cg);
            cpa16(dA,            Ah + goA);
            cpa16(dA + 2u * A_H, Al + goA);
            const long goB = (long)r * ldb + kt + cg;
            const uint32_t dB = st + 2u * (uint32_t)(2 * A_H + r * LDS + cg);
            cpa16(dB,            Bh + goB);
            cpa16(dB + 2u * B_H, Bl + goB);
        }
        cp_commit();
    };

    float acc[4][8][4];
    #pragma unroll
    for (int i = 0; i < 4; i++)
        #pragma unroll
        for (int j = 0; j < 8; j++)
            #pragma unroll
            for (int q = 0; q < 4; q++) acc[i][j][q] = 0.f;

    const int nt = K / 32;
    stage_copy(0, 0);

    for (int t = 0; t < nt; t++) {
        if (t + 1 < nt) stage_copy(t + 1, (t + 1) & 1);
        if (t + 1 < nt) asm volatile("cp.async.wait_group 1;" ::: "memory");
        else            asm volatile("cp.async.wait_group 0;" ::: "memory");
        __syncthreads();

        const int s = t & 1;
        const uint32_t ab = sb + 2u * (uint32_t)(s * STG);
        const uint32_t bb = ab + 2u * (uint32_t)(2 * A_H);

        #pragma unroll
        for (int ks = 0; ks < 2; ks++) {
            const int acol = ks * 16 + (lane >> 4) * 8;
            uint32_t afh[4][4], afl[4][4];
            #pragma unroll
            for (int mt = 0; mt < 4; mt++) {
                const uint32_t ad = ab + 2u * (uint32_t)((wm * 64 + mt * 16 + (lane & 15)) * LDS + acol);
                ldm4(afh[mt], ad);
                ldm4(afl[mt], ad + 2u * A_H);
            }
            #pragma unroll
            for (int p = 0; p < 4; p++) {
                uint32_t bfh[4], bfl[4];
                const int n = wn * 64 + (p * 2 + (bmat >> 1)) * 8 + bmr;
                const int koff = ks * 16 + (bmat & 1) * 8;
                const uint32_t bd = bb + 2u * (uint32_t)(n * LDS + koff);
                ldm4(bfh, bd);
                ldm4(bfl, bd + 2u * B_H);
                #pragma unroll
                for (int mt = 0; mt < 4; mt++) {
                    mma16816(acc[mt][2*p+0], afh[mt], bfh[0], bfh[1]);
                    mma16816(acc[mt][2*p+0], afh[mt], bfl[0], bfl[1]);
                    mma16816(acc[mt][2*p+0], afl[mt], bfh[0], bfh[1]);
                    mma16816(acc[mt][2*p+1], afh[mt], bfh[2], bfh[3]);
                    mma16816(acc[mt][2*p+1], afh[mt], bfl[2], bfl[3]);
                    mma16816(acc[mt][2*p+1], afl[mt], bfh[2], bfh[3]);
                }
            }
        }
        __syncthreads();
    }

    const int mW = mBlk + wm * 64;
    const int nW = nBlk + wn * 64;
    #pragma unroll
    for (int mt = 0; mt < 4; mt++) {
        #pragma unroll
        for (int n4 = 0; n4 < 8; n4++) {
            const int n0 = nW + n4 * 8 + (lane & 3) * 2;
            const float bx = bias[n0], by = bias[n0 + 1];
            #pragma unroll
            for (int half = 0; half < 2; half++) {
                const int m = mW + mt * 16 + half * 8 + (lane >> 2);
                float v0 = (acc[mt][n4][half * 2 + 0] + bx) * alpha;
                float v1 = (acc[mt][n4][half * 2 + 1] + by) * alpha;
                __nv_bfloat16 h0, h1, l0, l1;
                split2(v0, h0, l0); split2(v1, h1, l1);
                if (which < 2) {
                    const long ro = (long)m * ND + n0;
                    *reinterpret_cast<uint32_t*>(Chi + ro) = pack2(h0, h1);
                    *reinterpret_cast<uint32_t*>(Clo + ro) = pack2(l0, l1);
                } else {   // v transpose: vt[(b*512 + n)*512 + t]
                    const int bq2 = m >> 9, tq = m & 511;
                    const long a0 = ((long)(bq2 * 512 + n0)) * 512 + tq;
                    const long a1 = a0 + 512;
                    Chi[a0] = h0; Clo[a0] = l0;
                    Chi[a1] = h1; Clo[a1] = l1;
                }
            }
        }
    }
}

// ---------------- fused flash attention (unchanged from passing R12) -----------
__global__ __launch_bounds__(512, 1)
void flash_attn(const __nv_bfloat16* __restrict__ Qh, const __nv_bfloat16* __restrict__ Ql,
                const __nv_bfloat16* __restrict__ Kh, const __nv_bfloat16* __restrict__ Kl,
                const __nv_bfloat16* __restrict__ Vh, const __nv_bfloat16* __restrict__ Vl,
                __nv_bfloat16* __restrict__ Ch, __nv_bfloat16* __restrict__ Cl)
{
    constexpr int oQH = 0,      oQL = 18432;
    constexpr int oKH = 36864,  oKL = 55296;
    constexpr int oVH = 73728,  oVL = 91136;
    constexpr int oPH = 108544, oPL = 143360;
    constexpr int oPM = 178176, oPS = 180224;
    constexpr int oM  = 182272, oL = 182784, oS = 183296;
    extern __shared__ __align__(16) char smf[];
    const uint32_t sb = su32(smf);
    float* pm   = reinterpret_cast<float*>(smf + oPM);
    float* ps   = reinterpret_cast<float*>(smf + oPS);
    float* mrow = reinterpret_cast<float*>(smf + oM);
    float* lrow = reinterpret_cast<float*>(smf + oL);
    float* srow = reinterpret_cast<float*>(smf + oS);

    const int tid = threadIdx.x, wid = tid >> 5, lane = tid & 31;
    const int wm = wid >> 2, wn = wid & 3;
    const int om = wid >> 1, on = wid & 1;
    const int qt = blockIdx.x, z = blockIdx.y;
    const int b = z >> 3, h = z & 7;
    const int bmat = lane >> 3, bmr = lane & 7;

    {
        const long base = (long)(b * 512 + qt * 128) * 512 + h * 64;
        for (int i = tid; i < 1024; i += 512) {
            const int r = i >> 3, c8 = (i & 7) * 8;
            const long go = base + (long)r * 512 + c8;
            *reinterpret_cast<uint4*>(smf + oQH + 2 * (r * 72 + c8)) =
                *reinterpret_cast<const uint4*>(Qh + go);
            *reinterpret_cast<uint4*>(smf + oQL + 2 * (r * 72 + c8)) =
                *reinterpret_cast<const uint4*>(Ql + go);
        }
    }
    if (tid < 128) { mrow[tid] = -1e30f; lrow[tid] = 0.f; }

    float acc_o[4][4];
    #pragma unroll
    for (int i = 0; i < 4; i++)
        #pragma unroll
        for (int j = 0; j < 4; j++) acc_o[i][j] = 0.f;

    __syncthreads();

    for (int kb = 0; kb < 4; kb++) {
        {
            const long kbase = (long)(b * 512 + kb * 128) * 512 + h * 64;
            for (int i = tid; i < 1024; i += 512) {
                const int r = i >> 3, c8 = (i & 7) * 8;
                const long go = kbase + (long)r * 512 + c8;
                *reinterpret_cast<uint4*>(smf + oKH + 2 * (r * 72 + c8)) =
                    *reinterpret_cast<const uint4*>(Kh + go);
                *reinterpret_cast<uint4*>(smf + oKL + 2 * (r * 72 + c8)) =
                    *reinterpret_cast<const uint4*>(Kl + go);
            }
            const long vbase = (long)(b * 512 + h * 64) * 512 + kb * 128;
            for (int i = tid; i < 1024; i += 512) {
                const int r = i >> 4, c8 = (i & 15) * 8;
                const long go = vbase + (long)r * 512 + c8;
                *reinterpret_cast<uint4*>(smf + oVH + 2 * (r * 136 + c8)) =
                    *reinterpret_cast<const uint4*>(Vh + go);
                *reinterpret_cast<uint4*>(smf + oVL + 2 * (r * 136 + c8)) =
                    *reinterpret_cast<const uint4*>(Vl + go);
            }
        }
        __syncthreads();

        float acc_s[2][4][4];
        #pragma unroll
        for (int i = 0; i < 2; i++)
            #pragma unroll
            for (int j = 0; j < 4; j++)
                #pragma unroll
                for (int q = 0; q < 4; q++) acc_s[i][j][q] = 0.f;

        #pragma unroll
        for (int ks = 0; ks < 4; ks++) {
            const int acol = ks * 16 + (lane >> 4) * 8;
            uint32_t afh[2][4], afl[2][4];
            #pragma unroll
            for (int mt = 0; mt < 2; mt++) {
                const uint32_t ad = sb + oQH +
                    2u * (uint32_t)((wm * 32 + mt * 16 + (lane & 15)) * 72 + acol);
                ldm4(afh[mt], ad);
                ldm4(afl[mt], ad + (oQL - oQH));
            }
            uint32_t bfh[8], bfl[8];
            #pragma unroll
            for (int p = 0; p < 2; p++) {
                const int n = wn * 32 + (p * 2 + (bmat >> 1)) * 8 + bmr;
                const int koff = ks * 16 + (bmat & 1) * 8;
                const uint32_t bd = sb + oKH + 2u * (uint32_t)(n * 72 + koff);
                ldm4(&bfh[p * 4], bd);
                ldm4(&bfl[p * 4], bd + (oKL - oKH));
            }
            #pragma unroll
            for (int mt = 0; mt < 2; mt++) {
                #pragma unroll
                for (int n4 = 0; n4 < 4; n4++) {
                    const int bi = (n4 >> 1) * 4 + (n4 & 1) * 2;
                    mma16816(acc_s[mt][n4], afh[mt], bfh[bi], bfh[bi + 1]);
                    mma16816(acc_s[mt][n4], afh[mt], bfl[bi], bfl[bi + 1]);
                    mma16816(acc_s[mt][n4], afl[mt], bfh[bi], bfh[bi + 1]);
                }
            }
        }

        #pragma unroll
        for (int mt = 0; mt < 2; mt++) {
            #pragma unroll
            for (int half = 0; half < 2; half++) {
                float vmax = -1e30f;
                #pragma unroll
                for (int n4 = 0; n4 < 4; n4++)
                    vmax = fmaxf(vmax, fmaxf(acc_s[mt][n4][half * 2], acc_s[mt][n4][half * 2 + 1]));
                vmax = fmaxf(vmax, __shfl_xor_sync(0xffffffffu, vmax, 1));
                vmax = fmaxf(vmax, __shfl_xor_sync(0xffffffffu, vmax, 2));
                if ((lane & 3) == 0) {
                    const int row = wm * 32 + mt * 16 + half * 8 + (lane >> 2);
                    pm[row * 4 + wn] = vmax;
                }
            }
        }
        __syncthreads();
        if (tid < 128) {
            const float mb = fmaxf(fmaxf(pm[tid * 4], pm[tid * 4 + 1]),
                                   fmaxf(pm[tid * 4 + 2], pm[tid * 4 + 3]));
            const float mn = fmaxf(mrow[tid], mb);
            srow[tid] = __expf(mrow[tid] - mn);
            mrow[tid] = mn;
        }
        __syncthreads();

        #pragma unroll
        for (int mt = 0; mt < 2; mt++) {
            #pragma unroll
            for (int half = 0; half < 2; half++) {
                const int row = wm * 32 + mt * 16 + half * 8 + (lane >> 2);
                const float mi = mrow[row];
                float rs = 0.f;
                #pragma unroll
                for (int n4 = 0; n4 < 4; n4++) {
                    const float p0 = __expf(acc_s[mt][n4][half * 2 + 0] - mi);
                    const float p1 = __expf(acc_s[mt][n4][half * 2 + 1] - mi);
                    rs += p0 + p1;
                    const int col = wn * 32 + n4 * 8 + (lane & 3) * 2;
                    __nv_bfloat16 h0, h1, l0, l1;
                    split2(p0, h0, l0); split2(p1, h1, l1);
                    *reinterpret_cast<uint32_t*>(smf + oPH + 2 * (row * 136 + col)) = pack2(h0, h1);
                    *reinterpret_cast<uint32_t*>(smf + oPL + 2 * (row * 136 + col)) = pack2(l0, l1);
                }
                rs += __shfl_xor_sync(0xffffffffu, rs, 1);
                rs += __shfl_xor_sync(0xffffffffu, rs, 2);
                if ((lane & 3) == 0) ps[row * 4 + wn] = rs;
            }
        }
        __syncthreads();

        if (tid < 128)
            lrow[tid] = lrow[tid] * srow[tid] +
                        (ps[tid * 4] + ps[tid * 4 + 1] + ps[tid * 4 + 2] + ps[tid * 4 + 3]);

        {
            const int r0 = om * 16 + (lane >> 2);
            const float s0 = srow[r0], s1 = srow[r0 + 8];
            #pragma unroll
            for (int n4 = 0; n4 < 4; n4++) {
                acc_o[n4][0] *= s0; acc_o[n4][1] *= s0;
                acc_o[n4][2] *= s1; acc_o[n4][3] *= s1;
            }
        }

        #pragma unroll
        for (int ks2 = 0; ks2 < 8; ks2++) {
            const int acol = ks2 * 16 + (lane >> 4) * 8;
            uint32_t pah[4], pal[4];
            {
                const uint32_t ad = sb + oPH +
                    2u * (uint32_t)((om * 16 + (lane & 15)) * 136 + acol);
                ldm4(pah, ad);
                ldm4(pal, ad + (oPL - oPH));
            }
            uint32_t bfh[8], bfl[8];
            #pragma unroll
            for (int p = 0; p < 2; p++) {
                const int n = on * 32 + (p * 2 + (bmat >> 1)) * 8 + bmr;
                const int koff = ks2 * 16 + (bmat & 1) * 8;
                const uint32_t bd = sb + oVH + 2u * (uint32_t)(n * 136 + koff);
                ldm4(&bfh[p * 4], bd);
                ldm4(&bfl[p * 4], bd + (oVL - oVH));
            }
            #pragma unroll
            for (int n4 = 0; n4 < 4; n4++) {
                const int bi = (n4 >> 1) * 4 + (n4 & 1) * 2;
                mma16816(acc_o[n4], pah, bfh[bi], bfh[bi + 1]);
                mma16816(acc_o[n4], pah, bfl[bi], bfl[bi + 1]);
                mma16816(acc_o[n4], pal, bfh[bi], bfh[bi + 1]);
            }
        }
        __syncthreads();
    }

    if (tid < 128) srow[tid] = 1.f / lrow[tid];
    __syncthreads();
    {
        const int r0 = om * 16 + (lane >> 2);
        const float i0 = srow[r0], i1 = srow[r0 + 8];
        const long gq = (long)(b * 512 + qt * 128);
        #pragma unroll
        for (int n4 = 0; n4 < 4; n4++) {
            const int c0 = on * 32 + n4 * 8 + (lane & 3) * 2;
            const float v00 = acc_o[n4][0] * i0, v01 = acc_o[n4][1] * i0;
            const float v10 = acc_o[n4][2] * i1, v11 = acc_o[n4][3] * i1;
            const long a0 = (gq + r0) * 512 + h * 64 + c0;
            const long a1 = (gq + r0 + 8) * 512 + h * 64 + c0;
            __nv_bfloat16 h0, h1, l0, l1;
            split2(v00, h0, l0); split2(v01, h1, l1);
            *reinterpret_cast<uint32_t*>(Ch + a0) = pack2(h0, h1);
            *reinterpret_cast<uint32_t*>(Cl + a0) = pack2(l0, l1);
            split2(v10, h0, l0); split2(v11, h1, l1);
            *reinterpret_cast<uint32_t*>(Ch + a1) = pack2(h0, h1);
            *reinterpret_cast<uint32_t*>(Cl + a1) = pack2(l0, l1);
        }
    }
}

// ---------------- merged fp32 -> bf16 hi/lo split (all 8 tensors, 1 launch) ----
constexpr long C_X  = 2097152;
constexpr long C_WQ = C_X  + 65536;
constexpr long C_WK = C_WQ + 65536;
constexpr long C_WV = C_WK + 65536;
constexpr long C_WO = C_WV + 65536;
constexpr long C_W1 = C_WO + 32768;
constexpr long C_W2 = C_W1 + 16384;
constexpr long C_W3 = C_W2 + 32768;

__global__ __launch_bounds__(256)
void split_all(unsigned char* __restrict__ ar,
               const float* __restrict__ x,  const float* __restrict__ Wq,
               const float* __restrict__ Wk, const float* __restrict__ Wv,
               const float* __restrict__ Wo, const float* __restrict__ W1,
               const float* __restrict__ W2, const float* __restrict__ W3)
{
    const long i4 = (long)blockIdx.x * 256 + threadIdx.x;
    const float* src; size_t oh, ol; long l4; int rs = 0, cs = 0, cd = 0;
    if      (i4 < C_X)  { src = x;  oh = O_XH;  ol = O_XL;  l4 = i4; }
    else if (i4 < C_WQ) { src = Wq; oh = O_WQH; ol = O_WQL; l4 = i4 - C_X; }
    else if (i4 < C_WK) { src = Wk; oh = O_WKH; ol = O_WKL; l4 = i4 - C_WQ; }
    else if (i4 < C_WV) { src = Wv; oh = O_WVH; ol = O_WVL; l4 = i4 - C_WK; }
    else if (i4 < C_WO) { src = Wo; oh = O_WOH; ol = O_WOL; l4 = i4 - C_WV; }
    else if (i4 < C_W1) { src = W1; oh = O_W1H; ol = O_W1L; l4 = i4 - C_WO; rs = 200; cs = 512; cd = 512; }
    else if (i4 < C_W2) { src = W2; oh = O_W2H; ol = O_W2L; l4 = i4 - C_W1; rs = 200; cs = 200; cd = 256; }
    else                { src = W3; oh = O_W3H; ol = O_W3L; l4 = i4 - C_W2; rs = 512; cs = 200; cd = 256; }

    const long e = l4 * 4;
    float4 v = make_float4(0.f, 0.f, 0.f, 0.f);
    if (rs == 0) {
        v = *reinterpret_cast<const float4*>(src + e);
    } else {
        const int r = (int)(e / cd), c = (int)(e % cd);
        if (r < rs && c < cs)
            v = *reinterpret_cast<const float4*>(src + (long)r * cs + c);
    }
    __nv_bfloat16 h0, h1, h2, h3, l0, l1, l2, l3;
    split2(v.x, h0, l0); split2(v.y, h1, l1); split2(v.z, h2, l2); split2(v.w, h3, l3);
    *reinterpret_cast<uint2*>(reinterpret_cast<__nv_bfloat16*>(ar + oh) + e) =
        make_uint2(pack2(h0, h1), pack2(h2, h3));
    *reinterpret_cast<uint2*>(reinterpret_cast<__nv_bfloat16*>(ar + ol) + e) =
        make_uint2(pack2(l0, l1), pack2(l2, l3));
}

__global__ void pad_bias2(const float* __restrict__ s1, float* __restrict__ d1,
                          const float* __restrict__ s2, float* __restrict__ d2, int n) {
    const int i = threadIdx.x;
    if (blockIdx.x == 0) d1[i] = (i < n) ? s1[i] : 0.f;
    else                 d2[i] = (i < n) ? s2[i] : 0.f;
}

// ---------------- 2-D LayerNorm over (S,D) per batch ---------------------------
template<bool PAIR>
__global__ __launch_bounds__(1024)
void layernorm_kernel(const float* __restrict__ X,
                      const float* __restrict__ gamma, const float* __restrict__ beta,
                      float* __restrict__ out, __nv_bfloat16* __restrict__ oh,
                      __nv_bfloat16* __restrict__ ol)
{
    const long base = (long)blockIdx.x * LN_N;
    float s1 = 0.f, s2 = 0.f;
    for (int i = threadIdx.x * 4; i < LN_N; i += 4096) {
        float4 v = *reinterpret_cast<const float4*>(X + base + i);
        s1 += (v.x + v.y) + (v.z + v.w);
        s2 += (v.x*v.x + v.y*v.y) + (v.z*v.z + v.w*v.w);
    }
    __shared__ float r1[32], r2[32];
    const int lane = threadIdx.x & 31, wid = threadIdx.x >> 5;
    #pragma unroll
    for (int o = 16; o; o >>= 1) {
        s1 += __shfl_xor_sync(0xffffffffu, s1, o);
        s2 += __shfl_xor_sync(0xffffffffu, s2, o);
    }
    if (!lane) { r1[wid] = s1; r2[wid] = s2; }
    __syncthreads();
    if (threadIdx.x < 32) {
        s1 = r1[threadIdx.x]; s2 = r2[threadIdx.x];
        #pragma unroll
        for (int o = 16; o; o >>= 1) {
            s1 += __shfl_xor_sync(0xffffffffu, s1, o);
            s2 += __shfl_xor_sync(0xffffffffu, s2, o);
        }
        if (!threadIdx.x) { r1[0] = s1; r2[0] = s2; }
    }
    __syncthreads();
    const float mean = r1[0] / (float)LN_N;
    const float var  = r2[0] / (float)LN_N - mean * mean;
    const float rstd = rsqrtf(var + 1e-5f);

    for (int i = threadIdx.x * 4; i < LN_N; i += 4096) {
        float4 v = *reinterpret_cast<const float4*>(X + base + i);
        float4 g  = *reinterpret_cast<const float4*>(gamma + i);
        float4 bt = *reinterpret_cast<const float4*>(beta  + i);
        float4 o;
        o.x = (v.x - mean) * rstd * g.x + bt.x;
        o.y = (v.y - mean) * rstd * g.y + bt.y;
        o.z = (v.z - mean) * rstd * g.z + bt.z;
        o.w = (v.w - mean) * rstd * g.w + bt.w;
        *reinterpret_cast<float4*>(out + base + i) = o;
        if (PAIR) {
            __nv_bfloat16 h0, h1, h2, h3, l0, l1, l2, l3;
            split2(o.x, h0, l0); split2(o.y, h1, l1); split2(o.z, h2, l2); split2(o.w, h3, l3);
            *reinterpret_cast<uint2*>(oh + base + i) = make_uint2(pack2(h0, h1), pack2(h2, h3));
            *reinterpret_cast<uint2*>(ol + base + i) = make_uint2(pack2(l0, l1), pack2(l2, l3));
        }
    }
}

// ---------------- launch --------------------------------------------------------
extern "C" void kernel_launch(void* const* d_in, const int* in_sizes, int n_in,
                              void* d_out, int out_size)
{
    const float* x  = (const float*)d_in[0];
    const float* Wq = (const float*)d_in[1];
    const float* bq = (const float*)d_in[2];
    const float* Wk = (const float*)d_in[3];
    const float* bk = (const float*)d_in[4];
    const float* Wv = (const float*)d_in[5];
    const float* bv = (const float*)d_in[6];
    const float* Wo = (const float*)d_in[7];
    const float* bo = (const float*)d_in[8];
    const float* W1 = (const float*)d_in[9];
    const float* b1 = (const float*)d_in[10];
    const float* W2 = (const float*)d_in[11];
    const float* b2 = (const float*)d_in[12];
    const float* W3 = (const float*)d_in[13];
    const float* b3 = (const float*)d_in[14];
    const float* gamma = (const float*)d_in[15];
    const float* beta  = (const float*)d_in[16];
    float* out = (float*)d_out;

    unsigned char* ar;
    cudaGetSymbolAddress((void**)&ar, g_arena);
    #define BF(o) reinterpret_cast<__nv_bfloat16*>(ar + (o))
    #define FP(o) reinterpret_cast<float*>(ar + (o))

    const int SMG  = 2 * (2 * 128 * 40 + 2 * 128 * 40) * 2;   // 81920
    const int SMFL = 183808;
    cudaFuncSetAttribute((const void*)gemm_mma<0, false>, cudaFuncAttributeMaxDynamicSharedMemorySize, SMG);
    cudaFuncSetAttribute((const void*)gemm_mma<1, false>, cudaFuncAttributeMaxDynamicSharedMemorySize, SMG);
    cudaFuncSetAttribute((const void*)gemm_mma<1, true >, cudaFuncAttributeMaxDynamicSharedMemorySize, SMG);
    cudaFuncSetAttribute((const void*)qkv_mma, cudaFuncAttributeMaxDynamicSharedMemorySize, SMG);
    cudaFuncSetAttribute((const void*)flash_attn, cudaFuncAttributeMaxDynamicSharedMemorySize, SMFL);

    // ---- merged splits (one full-chip launch) + bias pads ----
    split_all<<<(unsigned)(C_W3 / 256), 256>>>(ar, x, Wq, Wk, Wv, Wo, W1, W2, W3);
    pad_bias2<<<2, 256>>>(b1, FP(O_B1P), b2, FP(O_B2P), NFF);

    // ---- 1) fused Q/K/V projections (one launch, 1536 CTAs) ----
    {
        dim3 grid(12, 128, 1);
        qkv_mma<<<grid, 128, SMG>>>(
            BF(O_XH), BF(O_XL),
            BF(O_WQH), BF(O_WQL), BF(O_WKH), BF(O_WKL), BF(O_WVH), BF(O_WVL),
            bq, bk, bv,
            BF(O_QH), BF(O_QL), BF(O_KH), BF(O_KL), BF(O_VTH), BF(O_VTL));
    }

    // ---- 2-4) fused flash attention -> concat pairs ----
    {
        dim3 grid(4, NB * NH);
        flash_attn<<<grid, 512, SMFL>>>(
            BF(O_QH), BF(O_QL), BF(O_KH), BF(O_KL),
            BF(O_VTH), BF(O_VTL), BF(O_CCH), BF(O_CCL));
    }

    // ---- 5) y = concat @ Wo^T + bo + x  (fp32) ----
    {
        dim3 grid(4, 128, 1);
        gemm_mma<0, false><<<grid, 128, SMG>>>(
            BF(O_CCH), BF(O_CCL), BF(O_WOH), BF(O_WOL), bo, x,
            FP(O_Y), nullptr, nullptr, ND, ND, ND, ND, 1.f);
    }

    // ---- 6) y = LN(y), also emit bf16 pair ----
    layernorm_kernel<true><<<NB, 1024>>>(FP(O_Y), gamma, beta,
                                         FP(O_Y), BF(O_YH), BF(O_YL));

    // ---- 7) f1 = relu(y @ W1p^T + b1p) pair, N=256 ----
    {
        dim3 grid(2, 128, 1);
        gemm_mma<1, true><<<grid, 128, SMG>>>(
            BF(O_YH), BF(O_YL), BF(O_W1H), BF(O_W1L), FP(O_B1P), nullptr,
            nullptr, BF(O_F1H), BF(O_F1L), ND, ND, ND, NFP, 1.f);
    }
    // ---- 8) f2 = relu(f1 @ W2p^T + b2p) pair, K=N=256 ----
    {
        dim3 grid(2, 128, 1);
        gemm_mma<1, true><<<grid, 128, SMG>>>(
            BF(O_F1H), BF(O_F1L), BF(O_W2H), BF(O_W2L), FP(O_B2P), nullptr,
            nullptr, BF(O_F2H), BF(O_F2L), NFP, NFP, NFP, NFP, 1.f);
    }
    // ---- 9) f3 = f2 @ W3p^T + b3 + y  (fp32, residual folded) ----
    {
        dim3 grid(4, 128, 1);
        gemm_mma<0, false><<<grid, 128, SMG>>>(
            BF(O_F2H), BF(O_F2L), BF(O_W3H), BF(O_W3L), b3, FP(O_Y),
            FP(O_F3), nullptr, nullptr, NFP, NFP, NFP, ND, 1.f);
    }

    // ---- 10) y2 = LN(f3)  (f3 already includes +y) ----
    layernorm_kernel<false><<<NB, 1024>>>(FP(O_F3), gamma, beta,
                                          FP(O_Y2), nullptr, nullptr);
    // ---- 11) out = LN(y2) ----
    layernorm_kernel<false><<<NB, 1024>>>(FP(O_Y2), gamma, beta,
                                          out, nullptr, nullptr);
}

// round 14
// speedup vs baseline: 1.4386x; 1.0225x over previous
#include <cuda_runtime.h>
#include <cuda_bf16.h>
#include <cstdint>

// ---------------- problem dims ------------------------------------------------
#define NB   32
#define NS   512
#define ND   512
#define NH   8
#define NDK  64
#define NFF  200
#define NFP  256            // padded FF width
#define NM   (NB * NS)      // 16384 rows
#define LN_N (NS * ND)      // 262144 elems per batch for 2-D LayerNorm

// ---------------- arena (single static device allocation) ---------------------
constexpr size_t SZ_BF_MD = (size_t)NM * ND * 2;        // [16384,512] bf16
constexpr size_t SZ_BF_DD = (size_t)ND * ND * 2;        // [512,512]  bf16
constexpr size_t SZ_BF_W1 = (size_t)NFP * ND * 2;
constexpr size_t SZ_BF_W2 = (size_t)NFP * NFP * 2;
constexpr size_t SZ_BF_W3 = (size_t)ND * NFP * 2;
constexpr size_t SZ_F_MD  = (size_t)NM * ND * 4;
constexpr size_t SZ_BF_MF = (size_t)NM * NFP * 2;

constexpr size_t O_XH = 0,                 O_XL = O_XH + SZ_BF_MD;
constexpr size_t O_WQH = O_XL + SZ_BF_MD,  O_WQL = O_WQH + SZ_BF_DD;
constexpr size_t O_WKH = O_WQL + SZ_BF_DD, O_WKL = O_WKH + SZ_BF_DD;
constexpr size_t O_WVH = O_WKL + SZ_BF_DD, O_WVL = O_WVH + SZ_BF_DD;
constexpr size_t O_WOH = O_WVL + SZ_BF_DD, O_WOL = O_WOH + SZ_BF_DD;
constexpr size_t O_W1H = O_WOL + SZ_BF_DD, O_W1L = O_W1H + SZ_BF_W1;
constexpr size_t O_W2H = O_W1L + SZ_BF_W1, O_W2L = O_W2H + SZ_BF_W2;
constexpr size_t O_W3H = O_W2L + SZ_BF_W2, O_W3L = O_W3H + SZ_BF_W3;
constexpr size_t O_B1P = O_W3L + SZ_BF_W3, O_B2P = O_B1P + 1024;
constexpr size_t O_QH  = O_B2P + 1024,     O_QL  = O_QH + SZ_BF_MD;
constexpr size_t O_KH  = O_QL + SZ_BF_MD,  O_KL  = O_KH + SZ_BF_MD;
constexpr size_t O_VTH = O_KL + SZ_BF_MD,  O_VTL = O_VTH + SZ_BF_MD;
constexpr size_t O_CCH = O_VTL + SZ_BF_MD, O_CCL = O_CCH + SZ_BF_MD;
constexpr size_t O_Y   = O_CCL + SZ_BF_MD;
constexpr size_t O_YH  = O_Y + SZ_F_MD,    O_YL  = O_YH + SZ_BF_MD;
constexpr size_t O_F1H = O_YL + SZ_BF_MD,  O_F1L = O_F1H + SZ_BF_MF;
constexpr size_t O_F2H = O_F1L + SZ_BF_MF, O_F2L = O_F2H + SZ_BF_MF;
constexpr size_t O_F3  = O_F2L + SZ_BF_MF;
constexpr size_t O_Y2  = O_F3 + SZ_F_MD;
constexpr size_t ARENA = O_Y2 + SZ_F_MD;

__device__ __align__(1024) unsigned char g_arena[ARENA];

// ---------------- helpers -----------------------------------------------------
__device__ __forceinline__ uint32_t su32(const void* p) {
    uint32_t a;
    asm("{ .reg .u64 t; cvta.to.shared.u64 t, %1; cvt.u32.u64 %0, t; }" : "=r"(a) : "l"(p));
    return a;
}
__device__ __forceinline__ void cpa16(uint32_t d, const void* s) {
    asm volatile("cp.async.ca.shared.global [%0], [%1], 16;" :: "r"(d), "l"(s));
}
__device__ __forceinline__ void cp_commit() {
    asm volatile("cp.async.commit_group;" ::: "memory");
}
__device__ __forceinline__ void ldm4(uint32_t* r, uint32_t a) {
    asm volatile("ldmatrix.sync.aligned.m8n8.x4.shared.b16 {%0,%1,%2,%3}, [%4];"
        : "=r"(r[0]), "=r"(r[1]), "=r"(r[2]), "=r"(r[3]) : "r"(a));
}
__device__ __forceinline__ void mma16816(float* c, const uint32_t* a, uint32_t b0, uint32_t b1) {
    asm volatile("mma.sync.aligned.m16n8k16.row.col.f32.bf16.bf16.f32 "
        "{%0,%1,%2,%3}, {%4,%5,%6,%7}, {%8,%9}, {%0,%1,%2,%3};"
        : "+f"(c[0]), "+f"(c[1]), "+f"(c[2]), "+f"(c[3])
        : "r"(a[0]), "r"(a[1]), "r"(a[2]), "r"(a[3]), "r"(b0), "r"(b1));
}
__device__ __forceinline__ void split2(float v, __nv_bfloat16& h, __nv_bfloat16& l) {
    h = __float2bfloat16(v);
    l = __float2bfloat16(v - __bfloat162float(h));
}
__device__ __forceinline__ uint32_t pack2(__nv_bfloat16 a, __nv_bfloat16 b) {
    return (uint32_t)__bfloat16_as_ushort(a) | ((uint32_t)__bfloat16_as_ushort(b) << 16);
}

// ---------------- bf16 HMMA GEMM: generic (Wo/W1/W2/W3 path) -------------------
template<int MODE, bool RELU>
__global__ __launch_bounds__(128, 2)
void gemm_mma(const __nv_bfloat16* __restrict__ Ah, const __nv_bfloat16* __restrict__ Al,
              const __nv_bfloat16* __restrict__ Bh, const __nv_bfloat16* __restrict__ Bl,
              const float* __restrict__ bias, const float* __restrict__ Res,
              float* __restrict__ Cf, __nv_bfloat16* __restrict__ Chi, __nv_bfloat16* __restrict__ Clo,
              int K, int lda, int ldb, int ldc,
              float alpha)
{
    constexpr int LDS = 40;
    constexpr int A_H = 128 * LDS;
    constexpr int B_H = 128 * LDS;
    constexpr int STG = 2 * A_H + 2 * B_H;

    extern __shared__ __align__(16) __nv_bfloat16 sm[];
    const uint32_t sb = su32(sm);

    const int tid = threadIdx.x, wid = tid >> 5, lane = tid & 31;
    const int wm = wid >> 1, wn = wid & 1;
    const int bmat = lane >> 3, bmr = lane & 7;

    const int mBlk = blockIdx.y * 128, nBlk = blockIdx.x * 128;
    Ah += (long)mBlk * lda; Al += (long)mBlk * lda;
    Bh += (long)nBlk * ldb; Bl += (long)nBlk * ldb;

    auto stage_copy = [&](int t, int s) {
        const int kt = t * 32;
        const uint32_t st = sb + 2u * (uint32_t)(s * STG);
        #pragma unroll
        for (int j = 0; j < 4; j++) {
            const int i = tid + j * 128;
            const int r = i >> 2, cg = (i & 3) * 8;
            const long goA = (long)r * lda + kt + cg;
            const uint32_t dA = st + 2u * (uint32_t)(r * LDS + cg);
            cpa16(dA,            Ah + goA);
            cpa16(dA + 2u * A_H, Al + goA);
            const long goB = (long)r * ldb + kt + cg;
            const uint32_t dB = st + 2u * (uint32_t)(2 * A_H + r * LDS + cg);
            cpa16(dB,            Bh + goB);
            cpa16(dB + 2u * B_H, Bl + goB);
        }
        cp_commit();
    };

    float acc[4][8][4];
    #pragma unroll
    for (int i = 0; i < 4; i++)
        #pragma unroll
        for (int j = 0; j < 8; j++)
            #pragma unroll
            for (int q = 0; q < 4; q++) acc[i][j][q] = 0.f;

    const int nt = K / 32;
    stage_copy(0, 0);

    for (int t = 0; t < nt; t++) {
        if (t + 1 < nt) stage_copy(t + 1, (t + 1) & 1);
        if (t + 1 < nt) asm volatile("cp.async.wait_group 1;" ::: "memory");
        else            asm volatile("cp.async.wait_group 0;" ::: "memory");
        __syncthreads();

        const int s = t & 1;
        const uint32_t ab = sb + 2u * (uint32_t)(s * STG);
        const uint32_t bb = ab + 2u * (uint32_t)(2 * A_H);

        #pragma unroll
        for (int ks = 0; ks < 2; ks++) {
            const int acol = ks * 16 + (lane >> 4) * 8;
            uint32_t afh[4][4], afl[4][4];
            #pragma unroll
            for (int mt = 0; mt < 4; mt++) {
                const uint32_t ad = ab + 2u * (uint32_t)((wm * 64 + mt * 16 + (lane & 15)) * LDS + acol);
                ldm4(afh[mt], ad);
                ldm4(afl[mt], ad + 2u * A_H);
            }
            #pragma unroll
            for (int p = 0; p < 4; p++) {
                uint32_t bfh[4], bfl[4];
                const int n = wn * 64 + (p * 2 + (bmat >> 1)) * 8 + bmr;
                const int koff = ks * 16 + (bmat & 1) * 8;
                const uint32_t bd = bb + 2u * (uint32_t)(n * LDS + koff);
                ldm4(bfh, bd);
                ldm4(bfl, bd + 2u * B_H);
                #pragma unroll
                for (int mt = 0; mt < 4; mt++) {
                    mma16816(acc[mt][2*p+0], afh[mt], bfh[0], bfh[1]);
                    mma16816(acc[mt][2*p+0], afh[mt], bfl[0], bfl[1]);
                    mma16816(acc[mt][2*p+0], afl[mt], bfh[0], bfh[1]);
                    mma16816(acc[mt][2*p+1], afh[mt], bfh[2], bfh[3]);
                    mma16816(acc[mt][2*p+1], afh[mt], bfl[2], bfl[3]);
                    mma16816(acc[mt][2*p+1], afl[mt], bfh[2], bfh[3]);
                }
            }
        }
        __syncthreads();
    }

    const int mW = mBlk + wm * 64;
    const int nW = nBlk + wn * 64;
    #pragma unroll
    for (int mt = 0; mt < 4; mt++) {
        #pragma unroll
        for (int n4 = 0; n4 < 8; n4++) {
            const int n0 = nW + n4 * 8 + (lane & 3) * 2;
            float bx = 0.f, by = 0.f;
            if (bias) { bx = bias[n0]; by = bias[n0 + 1]; }
            #pragma unroll
            for (int half = 0; half < 2; half++) {
                const int m = mW + mt * 16 + half * 8 + (lane >> 2);
                float v0 = acc[mt][n4][half * 2 + 0] + bx;
                float v1 = acc[mt][n4][half * 2 + 1] + by;
                v0 *= alpha; v1 *= alpha;
                if (RELU) { v0 = fmaxf(v0, 0.f); v1 = fmaxf(v1, 0.f); }
                if (MODE == 0) {
                    const long ro = (long)m * ldc + n0;
                    if (Res) { v0 += Res[ro]; v1 += Res[ro + 1]; }
                    *reinterpret_cast<float2*>(Cf + ro) = make_float2(v0, v1);
                } else {
                    const long ro = (long)m * ldc + n0;
                    __nv_bfloat16 h0, h1, l0, l1;
                    split2(v0, h0, l0); split2(v1, h1, l1);
                    *reinterpret_cast<uint32_t*>(Chi + ro) = pack2(h0, h1);
                    *reinterpret_cast<uint32_t*>(Clo + ro) = pack2(l0, l1);
                }
            }
        }
    }
}

// ---------------- fused QKV GEMM: one launch, grid (12, 128) --------------------
__global__ __launch_bounds__(128, 2)
void qkv_mma(const __nv_bfloat16* __restrict__ Ah, const __nv_bfloat16* __restrict__ Al,
             const __nv_bfloat16* __restrict__ WQh, const __nv_bfloat16* __restrict__ WQl,
             const __nv_bfloat16* __restrict__ WKh, const __nv_bfloat16* __restrict__ WKl,
             const __nv_bfloat16* __restrict__ WVh, const __nv_bfloat16* __restrict__ WVl,
             const float* __restrict__ bq, const float* __restrict__ bk, const float* __restrict__ bv,
             __nv_bfloat16* __restrict__ Qh, __nv_bfloat16* __restrict__ Ql,
             __nv_bfloat16* __restrict__ Kh, __nv_bfloat16* __restrict__ Kl,
             __nv_bfloat16* __restrict__ Vth, __nv_bfloat16* __restrict__ Vtl)
{
    constexpr int LDS = 40;
    constexpr int A_H = 128 * LDS;
    constexpr int B_H = 128 * LDS;
    constexpr int STG = 2 * A_H + 2 * B_H;
    constexpr int K = ND, lda = ND, ldb = ND;

    extern __shared__ __align__(16) __nv_bfloat16 sm[];
    const uint32_t sb = su32(sm);

    const int tid = threadIdx.x, wid = tid >> 5, lane = tid & 31;
    const int wm = wid >> 1, wn = wid & 1;
    const int bmat = lane >> 3, bmr = lane & 7;

    const int which = blockIdx.x >> 2;
    const int nBlk  = (blockIdx.x & 3) * 128;
    const int mBlk  = blockIdx.y * 128;

    const __nv_bfloat16* Bh = (which == 0) ? WQh : (which == 1) ? WKh : WVh;
    const __nv_bfloat16* Bl = (which == 0) ? WQl : (which == 1) ? WKl : WVl;
    const float* bias = (which == 0) ? bq : (which == 1) ? bk : bv;
    const float alpha = (which == 0) ? 0.125f : 1.f;
    __nv_bfloat16* Chi = (which == 0) ? Qh : (which == 1) ? Kh : Vth;
    __nv_bfloat16* Clo = (which == 0) ? Ql : (which == 1) ? Kl : Vtl;

    Ah += (long)mBlk * lda; Al += (long)mBlk * lda;
    Bh += (long)nBlk * ldb; Bl += (long)nBlk * ldb;

    auto stage_copy = [&](int t, int s) {
        const int kt = t * 32;
        const uint32_t st = sb + 2u * (uint32_t)(s * STG);
        #pragma unroll
        for (int j = 0; j < 4; j++) {
            const int i = tid + j * 128;
            const int r = i >> 2, cg = (i & 3) * 8;
            const long goA = (long)r * lda + kt + cg;
            const uint32_t dA = st + 2u * (uint32_t)(r * LDS + cg);
            cpa16(dA,            Ah + goA);
            cpa16(dA + 2u * A_H, Al + goA);
            const long goB = (long)r * ldb + kt + cg;
            const uint32_t dB = st + 2u * (uint32_t)(2 * A_H + r * LDS + cg);
            cpa16(dB,            Bh + goB);
            cpa16(dB + 2u * B_H, Bl + goB);
        }
        cp_commit();
    };

    float acc[4][8][4];
    #pragma unroll
    for (int i = 0; i < 4; i++)
        #pragma unroll
        for (int j = 0; j < 8; j++)
            #pragma unroll
            for (int q = 0; q < 4; q++) acc[i][j][q] = 0.f;

    const int nt = K / 32;
    stage_copy(0, 0);

    for (int t = 0; t < nt; t++) {
        if (t + 1 < nt) stage_copy(t + 1, (t + 1) & 1);
        if (t + 1 < nt) asm volatile("cp.async.wait_group 1;" ::: "memory");
        else            asm volatile("cp.async.wait_group 0;" ::: "memory");
        __syncthreads();

        const int s = t & 1;
        const uint32_t ab = sb + 2u * (uint32_t)(s * STG);
        const uint32_t bb = ab + 2u * (uint32_t)(2 * A_H);

        #pragma unroll
        for (int ks = 0; ks < 2; ks++) {
            const int acol = ks * 16 + (lane >> 4) * 8;
            uint32_t afh[4][4], afl[4][4];
            #pragma unroll
            for (int mt = 0; mt < 4; mt++) {
                const uint32_t ad = ab + 2u * (uint32_t)((wm * 64 + mt * 16 + (lane & 15)) * LDS + acol);
                ldm4(afh[mt], ad);
                ldm4(afl[mt], ad + 2u * A_H);
            }
            #pragma unroll
            for (int p = 0; p < 4; p++) {
                uint32_t bfh[4], bfl[4];
                const int n = wn * 64 + (p * 2 + (bmat >> 1)) * 8 + bmr;
                const int koff = ks * 16 + (bmat & 1) * 8;
                const uint32_t bd = bb + 2u * (uint32_t)(n * LDS + koff);
                ldm4(bfh, bd);
                ldm4(bfl, bd + 2u * B_H);
                #pragma unroll
                for (int mt = 0; mt < 4; mt++) {
                    mma16816(acc[mt][2*p+0], afh[mt], bfh[0], bfh[1]);
                    mma16816(acc[mt][2*p+0], afh[mt], bfl[0], bfl[1]);
                    mma16816(acc[mt][2*p+0], afl[mt], bfh[0], bfh[1]);
                    mma16816(acc[mt][2*p+1], afh[mt], bfh[2], bfh[3]);
                    mma16816(acc[mt][2*p+1], afh[mt], bfl[2], bfl[3]);
                    mma16816(acc[mt][2*p+1], afl[mt], bfh[2], bfh[3]);
                }
            }
        }
        __syncthreads();
    }

    const int mW = mBlk + wm * 64;
    const int nW = nBlk + wn * 64;
    #pragma unroll
    for (int mt = 0; mt < 4; mt++) {
        #pragma unroll
        for (int n4 = 0; n4 < 8; n4++) {
            const int n0 = nW + n4 * 8 + (lane & 3) * 2;
            const float bx = bias[n0], by = bias[n0 + 1];
            #pragma unroll
            for (int half = 0; half < 2; half++) {
                const int m = mW + mt * 16 + half * 8 + (lane >> 2);
                float v0 = (acc[mt][n4][half * 2 + 0] + bx) * alpha;
                float v1 = (acc[mt][n4][half * 2 + 1] + by) * alpha;
                __nv_bfloat16 h0, h1, l0, l1;
                split2(v0, h0, l0); split2(v1, h1, l1);
                if (which < 2) {
                    const long ro = (long)m * ND + n0;
                    *reinterpret_cast<uint32_t*>(Chi + ro) = pack2(h0, h1);
                    *reinterpret_cast<uint32_t*>(Clo + ro) = pack2(l0, l1);
                } else {
                    const int bq2 = m >> 9, tq = m & 511;
                    const long a0 = ((long)(bq2 * 512 + n0)) * 512 + tq;
                    const long a1 = a0 + 512;
                    Chi[a0] = h0; Clo[a0] = l0;
                    Chi[a1] = h1; Clo[a1] = l1;
                }
            }
        }
    }
}

// ---------------- fused flash attention v2 -------------------------------------
// CTA: 64 q-rows x one (b,h); 256 thr, 8 warps (4 row-groups x 2 col-halves).
// In-register P (C-frag -> A-frag), partial-O over k-halves, pair-reduce at end.
#define FL_SM 108800
__global__ __launch_bounds__(256, 2)
void flash_attn(const __nv_bfloat16* __restrict__ Qh, const __nv_bfloat16* __restrict__ Ql,
                const __nv_bfloat16* __restrict__ Kh, const __nv_bfloat16* __restrict__ Kl,
                const __nv_bfloat16* __restrict__ Vh, const __nv_bfloat16* __restrict__ Vl,
                __nv_bfloat16* __restrict__ Ch, __nv_bfloat16* __restrict__ Cl)
{
    constexpr int oQH = 0,     oQL = 9216;      // Q  [64][72]  halves
    constexpr int oKH = 18432, oKL = 36864;     // K  [128][72]
    constexpr int oVH = 55296, oVL = 72704;     // V^T[64][136]
    constexpr int oOR = 90112;                  // Ored [64][66] floats
    constexpr int oPM = 107008, oPS = 107520;   // [64][2] floats each
    constexpr int oM  = 108032, oL = 108288, oS = 108544;  // [64] floats
    extern __shared__ __align__(16) char smf[];
    const uint32_t sb = su32(smf);
    float* pm   = reinterpret_cast<float*>(smf + oPM);
    float* ps   = reinterpret_cast<float*>(smf + oPS);
    float* mrow = reinterpret_cast<float*>(smf + oM);
    float* lrow = reinterpret_cast<float*>(smf + oL);
    float* srow = reinterpret_cast<float*>(smf + oS);
    float* ored = reinterpret_cast<float*>(smf + oOR);

    const int tid = threadIdx.x, wid = tid >> 5, lane = tid & 31;
    const int wm = wid >> 1, wn = wid & 1;          // 4x2 warp grid
    const int qt = blockIdx.x, z = blockIdx.y;
    const int b = z >> 3, h = z & 7;
    const int bmat = lane >> 3, bmr = lane & 7;
    const int r0 = wm * 16 + (lane >> 2);           // this thread's base row

    // ---- load Q tile [64][64] hi/lo ----
    {
        const long base = (long)(b * 512 + qt * 64) * 512 + h * 64;
        for (int i = tid; i < 512; i += 256) {
            const int r = i >> 3, c8 = (i & 7) * 8;
            const long go = base + (long)r * 512 + c8;
            *reinterpret_cast<uint4*>(smf + oQH + 2 * (r * 72 + c8)) =
                *reinterpret_cast<const uint4*>(Qh + go);
            *reinterpret_cast<uint4*>(smf + oQL + 2 * (r * 72 + c8)) =
                *reinterpret_cast<const uint4*>(Ql + go);
        }
    }
    if (tid < 64) { mrow[tid] = -1e30f; lrow[tid] = 0.f; }

    float acc_o[8][4];
    #pragma unroll
    for (int i = 0; i < 8; i++)
        #pragma unroll
        for (int j = 0; j < 4; j++) acc_o[i][j] = 0.f;

    __syncthreads();

    for (int kb = 0; kb < 4; kb++) {
        // ---- load K block [128][64], V^T block [64][128] ----
        {
            const long kbase = (long)(b * 512 + kb * 128) * 512 + h * 64;
            for (int i = tid; i < 1024; i += 256) {
                const int r = i >> 3, c8 = (i & 7) * 8;
                const long go = kbase + (long)r * 512 + c8;
                *reinterpret_cast<uint4*>(smf + oKH + 2 * (r * 72 + c8)) =
                    *reinterpret_cast<const uint4*>(Kh + go);
                *reinterpret_cast<uint4*>(smf + oKL + 2 * (r * 72 + c8)) =
                    *reinterpret_cast<const uint4*>(Kl + go);
            }
            const long vbase = (long)(b * 512 + h * 64) * 512 + kb * 128;
            for (int i = tid; i < 1024; i += 256) {
                const int r = i >> 4, c8 = (i & 15) * 8;
                const long go = vbase + (long)r * 512 + c8;
                *reinterpret_cast<uint4*>(smf + oVH + 2 * (r * 136 + c8)) =
                    *reinterpret_cast<const uint4*>(Vh + go);
                *reinterpret_cast<uint4*>(smf + oVL + 2 * (r * 136 + c8)) =
                    *reinterpret_cast<const uint4*>(Vl + go);
            }
        }
        __syncthreads();

        // ---- GEMM1: warp computes scores [16 rows x 64 cols] ----
        float acc_s[8][4];
        #pragma unroll
        for (int i = 0; i < 8; i++)
            #pragma unroll
            for (int j = 0; j < 4; j++) acc_s[i][j] = 0.f;

        #pragma unroll
        for (int ks = 0; ks < 4; ks++) {
            const int acol = ks * 16 + (lane >> 4) * 8;
            uint32_t afh[4], afl[4];
            const uint32_t ad = sb + oQH +
                2u * (uint32_t)((wm * 16 + (lane & 15)) * 72 + acol);
            ldm4(afh, ad);
            ldm4(afl, ad + (oQL - oQH));
            #pragma unroll
            for (int p = 0; p < 4; p++) {
                uint32_t bfh[4], bfl[4];
                const int n = wn * 64 + (p * 2 + (bmat >> 1)) * 8 + bmr;
                const int koff = ks * 16 + (bmat & 1) * 8;
                const uint32_t bd = sb + oKH + 2u * (uint32_t)(n * 72 + koff);
                ldm4(bfh, bd);
                ldm4(bfl, bd + (oKL - oKH));
                mma16816(acc_s[2*p+0], afh, bfh[0], bfh[1]);
                mma16816(acc_s[2*p+0], afh, bfl[0], bfl[1]);
                mma16816(acc_s[2*p+0], afl, bfh[0], bfh[1]);
                mma16816(acc_s[2*p+1], afh, bfh[2], bfh[3]);
                mma16816(acc_s[2*p+1], afh, bfl[2], bfl[3]);
                mma16816(acc_s[2*p+1], afl, bfh[2], bfh[3]);
            }
        }

        // ---- row-max partials (2 col-halves per row) ----
        #pragma unroll
        for (int half = 0; half < 2; half++) {
            float vmax = -1e30f;
            #pragma unroll
            for (int n4 = 0; n4 < 8; n4++)
                vmax = fmaxf(vmax, fmaxf(acc_s[n4][half * 2], acc_s[n4][half * 2 + 1]));
            vmax = fmaxf(vmax, __shfl_xor_sync(0xffffffffu, vmax, 1));
            vmax = fmaxf(vmax, __shfl_xor_sync(0xffffffffu, vmax, 2));
            if ((lane & 3) == 0)
                pm[(wm * 16 + half * 8 + (lane >> 2)) * 2 + wn] = vmax;
        }
        __syncthreads();
        if (tid < 64) {
            const float mb = fmaxf(pm[tid * 2], pm[tid * 2 + 1]);
            const float mn = fmaxf(mrow[tid], mb);
            srow[tid] = __expf(mrow[tid] - mn);
            mrow[tid] = mn;
        }
        __syncthreads();

        // ---- P = exp(s - m) -> in-register A-frags; row-sum partials ----
        uint32_t pha[4][4], pla[4][4];
        {
            const float mi0 = mrow[r0], mi1 = mrow[r0 + 8];
            float rs0 = 0.f, rs1 = 0.f;
            #pragma unroll
            for (int n4 = 0; n4 < 8; n4++) {
                const float p00 = __expf(acc_s[n4][0] - mi0);
                const float p01 = __expf(acc_s[n4][1] - mi0);
                const float p10 = __expf(acc_s[n4][2] - mi1);
                const float p11 = __expf(acc_s[n4][3] - mi1);
                rs0 += p00 + p01;
                rs1 += p10 + p11;
                __nv_bfloat16 h0, h1, l0, l1;
                const int ks2 = n4 >> 1, sl = (n4 & 1) * 2;
                split2(p00, h0, l0); split2(p01, h1, l1);
                pha[ks2][sl + 0] = pack2(h0, h1);
                pla[ks2][sl + 0] = pack2(l0, l1);
                split2(p10, h0, l0); split2(p11, h1, l1);
                pha[ks2][sl + 1] = pack2(h0, h1);
                pla[ks2][sl + 1] = pack2(l0, l1);
            }
            rs0 += __shfl_xor_sync(0xffffffffu, rs0, 1);
            rs0 += __shfl_xor_sync(0xffffffffu, rs0, 2);
            rs1 += __shfl_xor_sync(0xffffffffu, rs1, 1);
            rs1 += __shfl_xor_sync(0xffffffffu, rs1, 2);
            if ((lane & 3) == 0) {
                ps[r0 * 2 + wn] = rs0;
                ps[(r0 + 8) * 2 + wn] = rs1;
            }
        }
        __syncthreads();

        if (tid < 64)
            lrow[tid] = lrow[tid] * srow[tid] + ps[tid * 2] + ps[tid * 2 + 1];

        // ---- rescale acc_o ----
        {
            const float s0 = srow[r0], s1 = srow[r0 + 8];
            #pragma unroll
            for (int n4 = 0; n4 < 8; n4++) {
                acc_o[n4][0] *= s0; acc_o[n4][1] *= s0;
                acc_o[n4][2] *= s1; acc_o[n4][3] *= s1;
            }
        }

        // ---- GEMM2: acc_o (partial over this warp's 64 keys) += P @ V^T ----
        #pragma unroll
        for (int ks2 = 0; ks2 < 4; ks2++) {
            #pragma unroll
            for (int p2 = 0; p2 < 4; p2++) {
                uint32_t bfh[4], bfl[4];
                const int n = (p2 * 2 + (bmat >> 1)) * 8 + bmr;
                const int koff = wn * 64 + ks2 * 16 + (bmat & 1) * 8;
                const uint32_t bd = sb + oVH + 2u * (uint32_t)(n * 136 + koff);
                ldm4(bfh, bd);
                ldm4(bfl, bd + (oVL - oVH));
                mma16816(acc_o[2*p2+0], pha[ks2], bfh[0], bfh[1]);
                mma16816(acc_o[2*p2+0], pha[ks2], bfl[0], bfl[1]);
                mma16816(acc_o[2*p2+0], pla[ks2], bfh[0], bfh[1]);
                mma16816(acc_o[2*p2+1], pha[ks2], bfh[2], bfh[3]);
                mma16816(acc_o[2*p2+1], pha[ks2], bfl[2], bfl[3]);
                mma16816(acc_o[2*p2+1], pla[ks2], bfh[2], bfh[3]);
            }
        }
        __syncthreads();
    }

    // ---- epilogue: pair-reduce partial O, divide by l, write pairs ----
    if (tid < 64) srow[tid] = 1.f / lrow[tid];
    if (wn == 0) {
        #pragma unroll
        for (int n4 = 0; n4 < 8; n4++) {
            const int c = n4 * 8 + (lane & 3) * 2;
            ored[r0 * 66 + c]       = acc_o[n4][0];
            ored[r0 * 66 + c + 1]   = acc_o[n4][1];
            ored[(r0+8) * 66 + c]     = acc_o[n4][2];
            ored[(r0+8) * 66 + c + 1] = acc_o[n4][3];
        }
    }
    __syncthreads();
    if (wn == 1) {
        const float i0 = srow[r0], i1 = srow[r0 + 8];
        const long gq = (long)(b * 512 + qt * 64);
        #pragma unroll
        for (int n4 = 0; n4 < 8; n4++) {
            const int c = n4 * 8 + (lane & 3) * 2;
            const float v00 = (acc_o[n4][0] + ored[r0 * 66 + c])     * i0;
            const float v01 = (acc_o[n4][1] + ored[r0 * 66 + c + 1]) * i0;
            const float v10 = (acc_o[n4][2] + ored[(r0+8) * 66 + c])     * i1;
            const float v11 = (acc_o[n4][3] + ored[(r0+8) * 66 + c + 1]) * i1;
            const long a0 = (gq + r0) * 512 + h * 64 + c;
            const long a1 = (gq + r0 + 8) * 512 + h * 64 + c;
            __nv_bfloat16 h0, h1, l0, l1;
            split2(v00, h0, l0); split2(v01, h1, l1);
            *reinterpret_cast<uint32_t*>(Ch + a0) = pack2(h0, h1);
            *reinterpret_cast<uint32_t*>(Cl + a0) = pack2(l0, l1);
            split2(v10, h0, l0); split2(v11, h1, l1);
            *reinterpret_cast<uint32_t*>(Ch + a1) = pack2(h0, h1);
            *reinterpret_cast<uint32_t*>(Cl + a1) = pack2(l0, l1);
        }
    }
}

// ---------------- merged fp32 -> bf16 hi/lo split (all 8 tensors, 1 launch) ----
constexpr long C_X  = 2097152;
constexpr long C_WQ = C_X  + 65536;
constexpr long C_WK = C_WQ + 65536;
constexpr long C_WV = C_WK + 65536;
constexpr long C_WO = C_WV + 65536;
constexpr long C_W1 = C_WO + 32768;
constexpr long C_W2 = C_W1 + 16384;
constexpr long C_W3 = C_W2 + 32768;

__global__ __launch_bounds__(256)
void split_all(unsigned char* __restrict__ ar,
               const float* __restrict__ x,  const float* __restrict__ Wq,
               const float* __restrict__ Wk, const float* __restrict__ Wv,
               const float* __restrict__ Wo, const float* __restrict__ W1,
               const float* __restrict__ W2, const float* __restrict__ W3)
{
    const long i4 = (long)blockIdx.x * 256 + threadIdx.x;
    const float* src; size_t oh, ol; long l4; int rs = 0, cs = 0, cd = 0;
    if      (i4 < C_X)  { src = x;  oh = O_XH;  ol = O_XL;  l4 = i4; }
    else if (i4 < C_WQ) { src = Wq; oh = O_WQH; ol = O_WQL; l4 = i4 - C_X; }
    else if (i4 < C_WK) { src = Wk; oh = O_WKH; ol = O_WKL; l4 = i4 - C_WQ; }
    else if (i4 < C_WV) { src = Wv; oh = O_WVH; ol = O_WVL; l4 = i4 - C_WK; }
    else if (i4 < C_WO) { src = Wo; oh = O_WOH; ol = O_WOL; l4 = i4 - C_WV; }
    else if (i4 < C_W1) { src = W1; oh = O_W1H; ol = O_W1L; l4 = i4 - C_WO; rs = 200; cs = 512; cd = 512; }
    else if (i4 < C_W2) { src = W2; oh = O_W2H; ol = O_W2L; l4 = i4 - C_W1; rs = 200; cs = 200; cd = 256; }
    else                { src = W3; oh = O_W3H; ol = O_W3L; l4 = i4 - C_W2; rs = 512; cs = 200; cd = 256; }

    const long e = l4 * 4;
    float4 v = make_float4(0.f, 0.f, 0.f, 0.f);
    if (rs == 0) {
        v = *reinterpret_cast<const float4*>(src + e);
    } else {
        const int r = (int)(e / cd), c = (int)(e % cd);
        if (r < rs && c < cs)
            v = *reinterpret_cast<const float4*>(src + (long)r * cs + c);
    }
    __nv_bfloat16 h0, h1, h2, h3, l0, l1, l2, l3;
    split2(v.x, h0, l0); split2(v.y, h1, l1); split2(v.z, h2, l2); split2(v.w, h3, l3);
    *reinterpret_cast<uint2*>(reinterpret_cast<__nv_bfloat16*>(ar + oh) + e) =
        make_uint2(pack2(h0, h1), pack2(h2, h3));
    *reinterpret_cast<uint2*>(reinterpret_cast<__nv_bfloat16*>(ar + ol) + e) =
        make_uint2(pack2(l0, l1), pack2(l2, l3));
}

__global__ void pad_bias2(const float* __restrict__ s1, float* __restrict__ d1,
                          const float* __restrict__ s2, float* __restrict__ d2, int n) {
    const int i = threadIdx.x;
    if (blockIdx.x == 0) d1[i] = (i < n) ? s1[i] : 0.f;
    else                 d2[i] = (i < n) ? s2[i] : 0.f;
}

// ---------------- 2-D LayerNorm over (S,D) per batch ---------------------------
template<bool PAIR>
__global__ __launch_bounds__(1024)
void layernorm_kernel(const float* __restrict__ X,
                      const float* __restrict__ gamma, const float* __restrict__ beta,
                      float* __restrict__ out, __nv_bfloat16* __restrict__ oh,
                      __nv_bfloat16* __restrict__ ol)
{
    const long base = (long)blockIdx.x * LN_N;
    float s1 = 0.f, s2 = 0.f;
    for (int i = threadIdx.x * 4; i < LN_N; i += 4096) {
        float4 v = *reinterpret_cast<const float4*>(X + base + i);
        s1 += (v.x + v.y) + (v.z + v.w);
        s2 += (v.x*v.x + v.y*v.y) + (v.z*v.z + v.w*v.w);
    }
    __shared__ float r1[32], r2[32];
    const int lane = threadIdx.x & 31, wid = threadIdx.x >> 5;
    #pragma unroll
    for (int o = 16; o; o >>= 1) {
        s1 += __shfl_xor_sync(0xffffffffu, s1, o);
        s2 += __shfl_xor_sync(0xffffffffu, s2, o);
    }
    if (!lane) { r1[wid] = s1; r2[wid] = s2; }
    __syncthreads();
    if (threadIdx.x < 32) {
        s1 = r1[threadIdx.x]; s2 = r2[threadIdx.x];
        #pragma unroll
        for (int o = 16; o; o >>= 1) {
            s1 += __shfl_xor_sync(0xffffffffu, s1, o);
            s2 += __shfl_xor_sync(0xffffffffu, s2, o);
        }
        if (!threadIdx.x) { r1[0] = s1; r2[0] = s2; }
    }
    __syncthreads();
    const float mean = r1[0] / (float)LN_N;
    const float var  = r2[0] / (float)LN_N - mean * mean;
    const float rstd = rsqrtf(var + 1e-5f);

    for (int i = threadIdx.x * 4; i < LN_N; i += 4096) {
        float4 v = *reinterpret_cast<const float4*>(X + base + i);
        float4 g  = *reinterpret_cast<const float4*>(gamma + i);
        float4 bt = *reinterpret_cast<const float4*>(beta  + i);
        float4 o;
        o.x = (v.x - mean) * rstd * g.x + bt.x;
        o.y = (v.y - mean) * rstd * g.y + bt.y;
        o.z = (v.z - mean) * rstd * g.z + bt.z;
        o.w = (v.w - mean) * rstd * g.w + bt.w;
        *reinterpret_cast<float4*>(out + base + i) = o;
        if (PAIR) {
            __nv_bfloat16 h0, h1, h2, h3, l0, l1, l2, l3;
            split2(o.x, h0, l0); split2(o.y, h1, l1); split2(o.z, h2, l2); split2(o.w, h3, l3);
            *reinterpret_cast<uint2*>(oh + base + i) = make_uint2(pack2(h0, h1), pack2(h2, h3));
            *reinterpret_cast<uint2*>(ol + base + i) = make_uint2(pack2(l0, l1), pack2(l2, l3));
        }
    }
}

// ---------------- launch --------------------------------------------------------
extern "C" void kernel_launch(void* const* d_in, const int* in_sizes, int n_in,
                              void* d_out, int out_size)
{
    const float* x  = (const float*)d_in[0];
    const float* Wq = (const float*)d_in[1];
    const float* bq = (const float*)d_in[2];
    const float* Wk = (const float*)d_in[3];
    const float* bk = (const float*)d_in[4];
    const float* Wv = (const float*)d_in[5];
    const float* bv = (const float*)d_in[6];
    const float* Wo = (const float*)d_in[7];
    const float* bo = (const float*)d_in[8];
    const float* W1 = (const float*)d_in[9];
    const float* b1 = (const float*)d_in[10];
    const float* W2 = (const float*)d_in[11];
    const float* b2 = (const float*)d_in[12];
    const float* W3 = (const float*)d_in[13];
    const float* b3 = (const float*)d_in[14];
    const float* gamma = (const float*)d_in[15];
    const float* beta  = (const float*)d_in[16];
    float* out = (float*)d_out;

    unsigned char* ar;
    cudaGetSymbolAddress((void**)&ar, g_arena);
    #define BF(o) reinterpret_cast<__nv_bfloat16*>(ar + (o))
    #define FP(o) reinterpret_cast<float*>(ar + (o))

    const int SMG = 2 * (2 * 128 * 40 + 2 * 128 * 40) * 2;   // 81920
    cudaFuncSetAttribute((const void*)gemm_mma<0, false>, cudaFuncAttributeMaxDynamicSharedMemorySize, SMG);
    cudaFuncSetAttribute((const void*)gemm_mma<1, false>, cudaFuncAttributeMaxDynamicSharedMemorySize, SMG);
    cudaFuncSetAttribute((const void*)gemm_mma<1, true >, cudaFuncAttributeMaxDynamicSharedMemorySize, SMG);
    cudaFuncSetAttribute((const void*)qkv_mma, cudaFuncAttributeMaxDynamicSharedMemorySize, SMG);
    cudaFuncSetAttribute((const void*)flash_attn, cudaFuncAttributeMaxDynamicSharedMemorySize, FL_SM);

    // ---- merged splits (one full-chip launch) + bias pads ----
    split_all<<<(unsigned)(C_W3 / 256), 256>>>(ar, x, Wq, Wk, Wv, Wo, W1, W2, W3);
    pad_bias2<<<2, 256>>>(b1, FP(O_B1P), b2, FP(O_B2P), NFF);

    // ---- 1) fused Q/K/V projections ----
    {
        dim3 grid(12, 128, 1);
        qkv_mma<<<grid, 128, SMG>>>(
            BF(O_XH), BF(O_XL),
            BF(O_WQH), BF(O_WQL), BF(O_WKH), BF(O_WKL), BF(O_WVH), BF(O_WVL),
            bq, bk, bv,
            BF(O_QH), BF(O_QL), BF(O_KH), BF(O_KL), BF(O_VTH), BF(O_VTL));
    }

    // ---- 2-4) fused flash attention v2 -> concat pairs ----
    {
        dim3 grid(8, NB * NH);
        flash_attn<<<grid, 256, FL_SM>>>(
            BF(O_QH), BF(O_QL), BF(O_KH), BF(O_KL),
            BF(O_VTH), BF(O_VTL), BF(O_CCH), BF(O_CCL));
    }

    // ---- 5) y = concat @ Wo^T + bo + x  (fp32) ----
    {
        dim3 grid(4, 128, 1);
        gemm_mma<0, false><<<grid, 128, SMG>>>(
            BF(O_CCH), BF(O_CCL), BF(O_WOH), BF(O_WOL), bo, x,
            FP(O_Y), nullptr, nullptr, ND, ND, ND, ND, 1.f);
    }

    // ---- 6) y = LN(y), also emit bf16 pair ----
    layernorm_kernel<true><<<NB, 1024>>>(FP(O_Y), gamma, beta,
                                         FP(O_Y), BF(O_YH), BF(O_YL));

    // ---- 7) f1 = relu(y @ W1p^T + b1p) pair, N=256 ----
    {
        dim3 grid(2, 128, 1);
        gemm_mma<1, true><<<grid, 128, SMG>>>(
            BF(O_YH), BF(O_YL), BF(O_W1H), BF(O_W1L), FP(O_B1P), nullptr,
            nullptr, BF(O_F1H), BF(O_F1L), ND, ND, ND, NFP, 1.f);
    }
    // ---- 8) f2 = relu(f1 @ W2p^T + b2p) pair, K=N=256 ----
    {
        dim3 grid(2, 128, 1);
        gemm_mma<1, true><<<grid, 128, SMG>>>(
            BF(O_F1H), BF(O_F1L), BF(O_W2H), BF(O_W2L), FP(O_B2P), nullptr,
            nullptr, BF(O_F2H), BF(O_F2L), NFP, NFP, NFP, NFP, 1.f);
    }
    // ---- 9) f3 = f2 @ W3p^T + b3 + y  (fp32, residual folded) ----
    {
        dim3 grid(4, 128, 1);
        gemm_mma<0, false><<<grid, 128, SMG>>>(
            BF(O_F2H), BF(O_F2L), BF(O_W3H), BF(O_W3L), b3, FP(O_Y),
            FP(O_F3), nullptr, nullptr, NFP, NFP, NFP, ND, 1.f);
    }

    // ---- 10) y2 = LN(f3)  (f3 already includes +y) ----
    layernorm_kernel<false><<<NB, 1024>>>(FP(O_F3), gamma, beta,
                                          FP(O_Y2), nullptr, nullptr);
    // ---- 11) out = LN(y2) ----
    layernorm_kernel<false><<<NB, 1024>>>(FP(O_Y2), gamma, beta,
                                          out, nullptr, nullptr);
}